// round 2
// baseline (speedup 1.0000x reference)
#include <cuda_runtime.h>
#include <math.h>

// Problem constants
constexpr int Bv = 4;
constexpr int Sv = 2048;
constexpr int Ev = 1024;
constexpr int Hv = 16;
constexpr int Dv = 64;
constexpr int BS = Bv * Sv;           // 8192 rows

// Scratch (allocation-free rule: __device__ globals)
__device__ float g_Q[BS * Ev];
__device__ float g_K[BS * Ev];
__device__ float g_V[BS * Ev];
__device__ float g_C[BS * Ev];        // attention context
__device__ float g_O[BS * Ev];        // main_out (pre-LN)

// ---------------------------------------------------------------------------
// Tiled SGEMM: C[M,N] = A[M,K] * W[K,N] + bias[N]
// M=8192, N=1024, K=1024.  64x64 block tile, 4x4 micro tile, K-step 16.
// ---------------------------------------------------------------------------
__global__ __launch_bounds__(256) void gemm_bias(const float* __restrict__ A,
                                                 const float* __restrict__ W,
                                                 const float* __restrict__ bias,
                                                 float* __restrict__ C) {
    __shared__ float As[16 * 68];   // [k][m], pitch 68 (16B-aligned rows, bank spread)
    __shared__ float Ws[16 * 64];   // [k][n], pitch 64

    const int tx = threadIdx.x & 15;
    const int ty = threadIdx.x >> 4;
    const int n0 = blockIdx.x * 64;
    const int m0 = blockIdx.y * 64;

    float acc[4][4] = {};

    for (int k0 = 0; k0 < 1024; k0 += 16) {
        #pragma unroll
        for (int e = threadIdx.x; e < 1024; e += 256) {
            int k = e & 15, m = e >> 4;
            As[k * 68 + m] = A[(size_t)(m0 + m) * 1024 + k0 + k];
        }
        #pragma unroll
        for (int e = threadIdx.x; e < 1024; e += 256) {
            int n = e & 63, k = e >> 6;
            Ws[k * 64 + n] = W[(size_t)(k0 + k) * 1024 + n0 + n];
        }
        __syncthreads();

        #pragma unroll
        for (int kk = 0; kk < 16; kk++) {
            float4 av = *(const float4*)&As[kk * 68 + ty * 4];
            float4 bv = *(const float4*)&Ws[kk * 64 + tx * 4];
            float a[4] = {av.x, av.y, av.z, av.w};
            float b[4] = {bv.x, bv.y, bv.z, bv.w};
            #pragma unroll
            for (int i = 0; i < 4; i++)
                #pragma unroll
                for (int j = 0; j < 4; j++)
                    acc[i][j] += a[i] * b[j];
        }
        __syncthreads();
    }

    #pragma unroll
    for (int i = 0; i < 4; i++) {
        int m = m0 + ty * 4 + i;
        int n = n0 + tx * 4;
        float4 o = make_float4(acc[i][0] + bias[n + 0],
                               acc[i][1] + bias[n + 1],
                               acc[i][2] + bias[n + 2],
                               acc[i][3] + bias[n + 3]);
        *(float4*)&C[(size_t)m * 1024 + n] = o;
    }
}

// ---------------------------------------------------------------------------
// Flash-attention style: 64 queries per block, 64-key tiles, online softmax.
// Layout in smem:  Qs[64][68], KPs[64][68] (K tile, reused for P), Vs[64][64], ms[64]
// ---------------------------------------------------------------------------
constexpr int QT = 64;
constexpr int KT = 64;
constexpr int QP = 68;   // padded pitch for Q / K-P buffers
constexpr int ATTN_SMEM = (QT * QP + KT * QP + KT * 64 + KT) * (int)sizeof(float);

__global__ __launch_bounds__(256) void attn_kernel(const float* __restrict__ Q,
                                                   const float* __restrict__ Kg,
                                                   const float* __restrict__ Vg,
                                                   const float* __restrict__ mask,
                                                   float* __restrict__ C) {
    extern __shared__ float sm[];
    float* Qs  = sm;                       // 64*68
    float* KPs = Qs + QT * QP;             // 64*68  (K tile, then P tile)
    float* Vs  = KPs + KT * QP;            // 64*64
    float* ms  = Vs + KT * 64;             // 64

    const int tid = threadIdx.x;
    const int tx = tid & 15;
    const int ty = tid >> 4;
    const int bh = blockIdx.y;
    const int b = bh / Hv, h = bh % Hv;
    const int q0 = blockIdx.x * QT;

    // Load Q tile (coalesced along d)
    for (int e = tid; e < QT * Dv; e += 256) {
        int r = e >> 6, d = e & 63;
        Qs[r * QP + d] = Q[((size_t)(b * Sv + q0 + r)) * Ev + h * Dv + d];
    }

    float acc[4][4] = {};
    float m_run[4], l_run[4];
    #pragma unroll
    for (int i = 0; i < 4; i++) { m_run[i] = -INFINITY; l_run[i] = 0.f; }

    for (int kt = 0; kt < Sv; kt += KT) {
        __syncthreads();   // previous tile's P/V reads done before overwrite
        for (int e = tid; e < KT * Dv; e += 256) {
            int r = e >> 6, d = e & 63;
            size_t g = ((size_t)(b * Sv + kt + r)) * Ev + h * Dv + d;
            KPs[r * QP + d] = Kg[g];
            Vs[r * 64 + d]  = Vg[g];
        }
        if (tid < KT) ms[tid] = mask[(size_t)b * Sv + kt + tid] * (-1e9f);
        __syncthreads();

        // ---- scores: s[i][j] = Q[ty*4+i][:] . K[tx*4+j][:]  ----
        float s[4][4] = {};
        #pragma unroll
        for (int d4 = 0; d4 < Dv / 4; d4++) {
            float4 av[4], bv[4];
            #pragma unroll
            for (int i = 0; i < 4; i++)
                av[i] = *(const float4*)&Qs[(ty * 4 + i) * QP + d4 * 4];
            #pragma unroll
            for (int j = 0; j < 4; j++)
                bv[j] = *(const float4*)&KPs[(tx * 4 + j) * QP + d4 * 4];
            #pragma unroll
            for (int i = 0; i < 4; i++)
                #pragma unroll
                for (int j = 0; j < 4; j++)
                    s[i][j] += av[i].x * bv[j].x + av[i].y * bv[j].y
                             + av[i].z * bv[j].z + av[i].w * bv[j].w;
        }

        // ---- online softmax (row r = ty*4+i owned by the 16 tx lanes) ----
        #pragma unroll
        for (int i = 0; i < 4; i++) {
            float mx = -INFINITY;
            #pragma unroll
            for (int j = 0; j < 4; j++) {
                s[i][j] = s[i][j] * 0.03125f + ms[tx * 4 + j];   // 1/sqrt(1024)
                mx = fmaxf(mx, s[i][j]);
            }
            #pragma unroll
            for (int o = 8; o > 0; o >>= 1)
                mx = fmaxf(mx, __shfl_xor_sync(0xffffffffu, mx, o));
            float m_new = fmaxf(m_run[i], mx);
            float alpha = __expf(m_run[i] - m_new);
            float rs = 0.f;
            #pragma unroll
            for (int j = 0; j < 4; j++) {
                s[i][j] = __expf(s[i][j] - m_new);
                rs += s[i][j];
            }
            #pragma unroll
            for (int o = 8; o > 0; o >>= 1)
                rs += __shfl_xor_sync(0xffffffffu, rs, o);
            l_run[i] = l_run[i] * alpha + rs;
            m_run[i] = m_new;
            #pragma unroll
            for (int j = 0; j < 4; j++) acc[i][j] *= alpha;
        }

        __syncthreads();   // all score reads of KPs done; safe to overwrite with P
        #pragma unroll
        for (int i = 0; i < 4; i++) {
            float4 pv = make_float4(s[i][0], s[i][1], s[i][2], s[i][3]);
            *(float4*)&KPs[(ty * 4 + i) * QP + tx * 4] = pv;
        }
        __syncthreads();

        // ---- acc[i][j] += sum_k P[ty*4+i][k] * V[k][tx*4+j] ----
        #pragma unroll
        for (int k = 0; k < KT; k++) {
            float4 bv = *(const float4*)&Vs[k * 64 + tx * 4];
            #pragma unroll
            for (int i = 0; i < 4; i++) {
                float a = KPs[(ty * 4 + i) * QP + k];
                acc[i][0] += a * bv.x; acc[i][1] += a * bv.y;
                acc[i][2] += a * bv.z; acc[i][3] += a * bv.w;
            }
        }
    }

    #pragma unroll
    for (int i = 0; i < 4; i++) {
        float inv = 1.f / l_run[i];
        int r = q0 + ty * 4 + i;
        float4 o = make_float4(acc[i][0] * inv, acc[i][1] * inv,
                               acc[i][2] * inv, acc[i][3] * inv);
        *(float4*)&C[((size_t)(b * Sv + r)) * Ev + h * Dv + tx * 4] = o;
    }
}

// ---------------------------------------------------------------------------
// LayerNorm(main_out + x) * gamma + beta.  One block per row, 256 threads.
// ---------------------------------------------------------------------------
__global__ __launch_bounds__(256) void ln_kernel(const float* __restrict__ MO,
                                                 const float* __restrict__ X,
                                                 const float* __restrict__ gamma,
                                                 const float* __restrict__ beta,
                                                 float* __restrict__ out) {
    const int r = blockIdx.x;
    const float* mo = MO + (size_t)r * Ev;
    const float* xr = X + (size_t)r * Ev;

    float v[4];
    float s1 = 0.f, s2 = 0.f;
    #pragma unroll
    for (int i = 0; i < 4; i++) {
        int idx = threadIdx.x + i * 256;
        v[i] = mo[idx] + xr[idx];
        s1 += v[i];
        s2 += v[i] * v[i];
    }
    #pragma unroll
    for (int o = 16; o > 0; o >>= 1) {
        s1 += __shfl_xor_sync(0xffffffffu, s1, o);
        s2 += __shfl_xor_sync(0xffffffffu, s2, o);
    }
    __shared__ float sh1[8], sh2[8], stats[2];
    const int w = threadIdx.x >> 5, lane = threadIdx.x & 31;
    if (lane == 0) { sh1[w] = s1; sh2[w] = s2; }
    __syncthreads();
    if (threadIdx.x == 0) {
        float t1 = 0.f, t2 = 0.f;
        #pragma unroll
        for (int i = 0; i < 8; i++) { t1 += sh1[i]; t2 += sh2[i]; }
        float mu = t1 * (1.f / Ev);
        float var = t2 * (1.f / Ev) - mu * mu;
        stats[0] = mu;
        stats[1] = rsqrtf(var + 1e-6f);
    }
    __syncthreads();
    const float mu = stats[0], rstd = stats[1];
    #pragma unroll
    for (int i = 0; i < 4; i++) {
        int idx = threadIdx.x + i * 256;
        out[(size_t)r * Ev + idx] = gamma[idx] * (v[i] - mu) * rstd + beta[idx];
    }
}

// ---------------------------------------------------------------------------
extern "C" void kernel_launch(void* const* d_in, const int* in_sizes, int n_in,
                              void* d_out, int out_size) {
    const float* x     = (const float*)d_in[0];
    const float* mask  = (const float*)d_in[1];
    const float* Wq    = (const float*)d_in[2];
    const float* bq    = (const float*)d_in[3];
    const float* Wk    = (const float*)d_in[4];
    const float* bk    = (const float*)d_in[5];
    const float* Wv    = (const float*)d_in[6];
    const float* bv    = (const float*)d_in[7];
    const float* Wo    = (const float*)d_in[8];
    const float* bo    = (const float*)d_in[9];
    const float* gamma = (const float*)d_in[10];
    const float* beta  = (const float*)d_in[11];
    float* out = (float*)d_out;

    float *Qb, *Kb, *Vb, *Cb, *Ob;
    cudaGetSymbolAddress((void**)&Qb, g_Q);
    cudaGetSymbolAddress((void**)&Kb, g_K);
    cudaGetSymbolAddress((void**)&Vb, g_V);
    cudaGetSymbolAddress((void**)&Cb, g_C);
    cudaGetSymbolAddress((void**)&Ob, g_O);

    cudaFuncSetAttribute(attn_kernel,
                         cudaFuncAttributeMaxDynamicSharedMemorySize, ATTN_SMEM);

    dim3 gg(Ev / 64, BS / 64);   // (16, 128)
    gemm_bias<<<gg, 256>>>(x, Wq, bq, Qb);
    gemm_bias<<<gg, 256>>>(x, Wk, bk, Kb);
    gemm_bias<<<gg, 256>>>(x, Wv, bv, Vb);

    attn_kernel<<<dim3(Sv / QT, Bv * Hv), 256, ATTN_SMEM>>>(Qb, Kb, Vb, mask, Cb);

    gemm_bias<<<gg, 256>>>(Cb, Wo, bo, Ob);

    ln_kernel<<<BS, 256>>>(Ob, x, gamma, beta, out);
}

// round 6
// speedup vs baseline: 3.8497x; 3.8497x over previous
#include <cuda_runtime.h>
#include <cstdint>
#include <math.h>

// Problem constants
constexpr int Bv = 4;
constexpr int Sv = 2048;
constexpr int Ev = 1024;
constexpr int Hv = 16;
constexpr int Dv = 64;
constexpr int BS = Bv * Sv;           // 8192 rows

// Scratch (allocation-free rule: __device__ globals)
__device__ float g_Q[BS * Ev];
__device__ float g_K[BS * Ev];
__device__ float g_V[BS * Ev];
__device__ float g_C[BS * Ev];        // attention context
__device__ float g_O[BS * Ev];        // main_out (pre-LN)

// ---------------------------------------------------------------------------
// tf32 helpers (portable PTX: sm_80+, compiles under compute_103)
// ---------------------------------------------------------------------------
__device__ __forceinline__ float tf32r(float f) {
    uint32_t r;
    asm("cvt.rna.tf32.f32 %0, %1;" : "=r"(r) : "f"(f));
    return __uint_as_float(r);
}

// D += A(16x8) * B(8x8), tf32 inputs, f32 accum
__device__ __forceinline__ void mma8(float* d, uint32_t a0, uint32_t a1,
                                     uint32_t a2, uint32_t a3,
                                     uint32_t b0, uint32_t b1) {
    asm volatile(
        "mma.sync.aligned.m16n8k8.row.col.f32.tf32.tf32.f32 "
        "{%0,%1,%2,%3}, {%4,%5,%6,%7}, {%8,%9}, {%0,%1,%2,%3};"
        : "+f"(d[0]), "+f"(d[1]), "+f"(d[2]), "+f"(d[3])
        : "r"(a0), "r"(a1), "r"(a2), "r"(a3), "r"(b0), "r"(b1));
}

__device__ __forceinline__ uint32_t fb(float f) { return __float_as_uint(f); }

// ---------------------------------------------------------------------------
// tf32 mma GEMM: C[8192,1024] = A[8192,1024] @ W[1024,1024] + bias
// CTA tile 128x128, 8 warps (2 M x 4 N), warp tile 64x32.
// K-chunk 32, register-staged pipeline. W consumed in natural [K,N] layout.
// ---------------------------------------------------------------------------
constexpr int PAs = 36;    // As pitch (floats): bank = gid*4+tig (unique)
constexpr int PBs = 136;   // Bs pitch (floats): bank = tig*8+gid (unique)

__global__ __launch_bounds__(256) void gemm_tc(const float* __restrict__ A,
                                               const float* __restrict__ W,
                                               const float* __restrict__ bias,
                                               float* __restrict__ C) {
    __shared__ float As[128 * PAs];   // [m][k]
    __shared__ float Bs[32 * PBs];    // [k][n]

    const int tid = threadIdx.x, wid = tid >> 5, lane = tid & 31;
    const int gid = lane >> 2, tig = lane & 3;
    const int wm = wid >> 2, wn = wid & 3;        // 2 x 4 warp grid
    const int m0 = blockIdx.y * 128, n0 = blockIdx.x * 128;

    float acc[4][4][4] = {};
    float4 stA[4], stB[4];

    // prologue: load chunk 0
    #pragma unroll
    for (int i = 0; i < 4; i++) {
        int idx = tid + i * 256, r = idx >> 3, k4 = idx & 7;
        stA[i] = *(const float4*)(A + (size_t)(m0 + r) * 1024 + k4 * 4);
    }
    #pragma unroll
    for (int i = 0; i < 4; i++) {
        int idx = tid + i * 256, kk = idx >> 5, n4 = idx & 31;
        stB[i] = *(const float4*)(W + (size_t)kk * 1024 + n0 + n4 * 4);
    }
    #pragma unroll
    for (int i = 0; i < 4; i++) {
        int idx = tid + i * 256, r = idx >> 3, k4 = idx & 7;
        float* p = &As[r * PAs + k4 * 4];
        p[0] = tf32r(stA[i].x); p[1] = tf32r(stA[i].y);
        p[2] = tf32r(stA[i].z); p[3] = tf32r(stA[i].w);
    }
    #pragma unroll
    for (int i = 0; i < 4; i++) {
        int idx = tid + i * 256, kk = idx >> 5, n4 = idx & 31;
        float* p = &Bs[kk * PBs + n4 * 4];
        p[0] = tf32r(stB[i].x); p[1] = tf32r(stB[i].y);
        p[2] = tf32r(stB[i].z); p[3] = tf32r(stB[i].w);
    }
    __syncthreads();

    for (int c = 0; c < 32; c++) {
        if (c + 1 < 32) {   // prefetch next chunk into registers
            #pragma unroll
            for (int i = 0; i < 4; i++) {
                int idx = tid + i * 256, r = idx >> 3, k4 = idx & 7;
                stA[i] = *(const float4*)(A + (size_t)(m0 + r) * 1024 + (c + 1) * 32 + k4 * 4);
            }
            #pragma unroll
            for (int i = 0; i < 4; i++) {
                int idx = tid + i * 256, kk = idx >> 5, n4 = idx & 31;
                stB[i] = *(const float4*)(W + (size_t)((c + 1) * 32 + kk) * 1024 + n0 + n4 * 4);
            }
        }
        // compute 4 k8-steps from smem
        #pragma unroll
        for (int kk = 0; kk < 4; kk++) {
            const int k0 = kk * 8;
            uint32_t af[4][4], bf[4][2];
            #pragma unroll
            for (int mt = 0; mt < 4; mt++) {
                int row = wm * 64 + mt * 16 + gid;
                af[mt][0] = fb(As[row * PAs + k0 + tig]);
                af[mt][1] = fb(As[(row + 8) * PAs + k0 + tig]);
                af[mt][2] = fb(As[row * PAs + k0 + tig + 4]);
                af[mt][3] = fb(As[(row + 8) * PAs + k0 + tig + 4]);
            }
            #pragma unroll
            for (int nt = 0; nt < 4; nt++) {
                int col = wn * 32 + nt * 8 + gid;
                bf[nt][0] = fb(Bs[(k0 + tig) * PBs + col]);
                bf[nt][1] = fb(Bs[(k0 + tig + 4) * PBs + col]);
            }
            #pragma unroll
            for (int mt = 0; mt < 4; mt++)
                #pragma unroll
                for (int nt = 0; nt < 4; nt++)
                    mma8(acc[mt][nt], af[mt][0], af[mt][1], af[mt][2], af[mt][3],
                         bf[nt][0], bf[nt][1]);
        }
        __syncthreads();
        if (c + 1 < 32) {
            #pragma unroll
            for (int i = 0; i < 4; i++) {
                int idx = tid + i * 256, r = idx >> 3, k4 = idx & 7;
                float* p = &As[r * PAs + k4 * 4];
                p[0] = tf32r(stA[i].x); p[1] = tf32r(stA[i].y);
                p[2] = tf32r(stA[i].z); p[3] = tf32r(stA[i].w);
            }
            #pragma unroll
            for (int i = 0; i < 4; i++) {
                int idx = tid + i * 256, kk = idx >> 5, n4 = idx & 31;
                float* p = &Bs[kk * PBs + n4 * 4];
                p[0] = tf32r(stB[i].x); p[1] = tf32r(stB[i].y);
                p[2] = tf32r(stB[i].z); p[3] = tf32r(stB[i].w);
            }
            __syncthreads();
        }
    }

    // epilogue: bias + store
    #pragma unroll
    for (int mt = 0; mt < 4; mt++) {
        int row = m0 + wm * 64 + mt * 16 + gid;
        #pragma unroll
        for (int nt = 0; nt < 4; nt++) {
            int col = n0 + wn * 32 + nt * 8 + tig * 2;
            float b0 = bias[col], b1 = bias[col + 1];
            *(float2*)(C + (size_t)row * 1024 + col) =
                make_float2(acc[mt][nt][0] + b0, acc[mt][nt][1] + b1);
            *(float2*)(C + (size_t)(row + 8) * 1024 + col) =
                make_float2(acc[mt][nt][2] + b0, acc[mt][nt][3] + b1);
        }
    }
}

// ---------------------------------------------------------------------------
// Flash attention on mma.sync tf32.
// CTA: 128 queries of one (b,h); 16 key-tiles of 128.
// S: warp tile 64x32 (2x4 grid).  PV: warp tile 64x16 (2x4 over d).
// K and V consumed row-major [key][d] directly as .col B operands.
// smem: Qs[128x68] Ks[128x68] Vs[128x72] Ps[128x132] mask[128] alpha[128]
// ---------------------------------------------------------------------------
constexpr int PQs = 68, PKs = 68, PVs = 72, PPs = 132;
constexpr int ATTN_SMEM = (128 * PQs + 128 * PKs + 128 * PVs + 128 * PPs + 256) * 4;

__global__ __launch_bounds__(256) void attn_tc(const float* __restrict__ Q,
                                               const float* __restrict__ Kg,
                                               const float* __restrict__ Vg,
                                               const float* __restrict__ mask,
                                               float* __restrict__ C) {
    extern __shared__ float smf[];
    float* Qs = smf;
    float* Ks = Qs + 128 * PQs;
    float* Vs = Ks + 128 * PKs;
    float* Ps = Vs + 128 * PVs;
    float* sMask = Ps + 128 * PPs;
    float* sAlpha = sMask + 128;

    const int tid = threadIdx.x, wid = tid >> 5, lane = tid & 31;
    const int gid = lane >> 2, tig = lane & 3;
    const int wm = wid >> 2, wn = wid & 3;
    const int b = blockIdx.y >> 4, h = blockIdx.y & 15;
    const int q0 = blockIdx.x * 128;
    const int sr = tid >> 1, sh = tid & 1;   // softmax row / half
    const float scale = 0.03125f;            // 1/sqrt(1024)

    // load Q tile (tf32-rounded)
    {
        const float* Qg = Q + ((size_t)(b * Sv + q0)) * Ev + h * 64;
        #pragma unroll
        for (int i = 0; i < 8; i++) {
            int idx = tid + i * 256, r = idx >> 4, d4 = idx & 15;
            float4 v = *(const float4*)(Qg + (size_t)r * Ev + d4 * 4);
            float* p = &Qs[r * PQs + d4 * 4];
            p[0] = tf32r(v.x); p[1] = tf32r(v.y); p[2] = tf32r(v.z); p[3] = tf32r(v.w);
        }
    }

    float o[4][2][4] = {};
    float m_run = -INFINITY, l_run = 0.f;

    for (int kt = 0; kt < Sv; kt += 128) {
        // ---- load K, V tiles ----
        const float* Kp = Kg + ((size_t)(b * Sv + kt)) * Ev + h * 64;
        const float* Vp = Vg + ((size_t)(b * Sv + kt)) * Ev + h * 64;
        #pragma unroll
        for (int i = 0; i < 8; i++) {
            int idx = tid + i * 256, r = idx >> 4, d4 = idx & 15;
            float4 kv = *(const float4*)(Kp + (size_t)r * Ev + d4 * 4);
            float4 vv = *(const float4*)(Vp + (size_t)r * Ev + d4 * 4);
            float* pk = &Ks[r * PKs + d4 * 4];
            float* pv = &Vs[r * PVs + d4 * 4];
            pk[0] = tf32r(kv.x); pk[1] = tf32r(kv.y); pk[2] = tf32r(kv.z); pk[3] = tf32r(kv.w);
            pv[0] = tf32r(vv.x); pv[1] = tf32r(vv.y); pv[2] = tf32r(vv.z); pv[3] = tf32r(vv.w);
        }
        if (tid < 128) sMask[tid] = mask[(size_t)b * Sv + kt + tid] * (-1e9f);
        __syncthreads();

        // ---- S = Q @ K^T (warp tile 64 q x 32 keys) ----
        float s[4][4][4] = {};
        #pragma unroll
        for (int kk = 0; kk < 8; kk++) {
            const int k0 = kk * 8;
            uint32_t af[4][4], bf[4][2];
            #pragma unroll
            for (int mt = 0; mt < 4; mt++) {
                int row = wm * 64 + mt * 16 + gid;
                af[mt][0] = fb(Qs[row * PQs + k0 + tig]);
                af[mt][1] = fb(Qs[(row + 8) * PQs + k0 + tig]);
                af[mt][2] = fb(Qs[row * PQs + k0 + tig + 4]);
                af[mt][3] = fb(Qs[(row + 8) * PQs + k0 + tig + 4]);
            }
            #pragma unroll
            for (int nt = 0; nt < 4; nt++) {
                int key = wn * 32 + nt * 8 + gid;
                bf[nt][0] = fb(Ks[key * PKs + k0 + tig]);
                bf[nt][1] = fb(Ks[key * PKs + k0 + tig + 4]);
            }
            #pragma unroll
            for (int mt = 0; mt < 4; mt++)
                #pragma unroll
                for (int nt = 0; nt < 4; nt++)
                    mma8(s[mt][nt], af[mt][0], af[mt][1], af[mt][2], af[mt][3],
                         bf[nt][0], bf[nt][1]);
        }
        // store scaled+masked scores
        #pragma unroll
        for (int mt = 0; mt < 4; mt++) {
            int row = wm * 64 + mt * 16 + gid;
            #pragma unroll
            for (int nt = 0; nt < 4; nt++) {
                int col = wn * 32 + nt * 8 + tig * 2;
                float ms0 = sMask[col], ms1 = sMask[col + 1];
                Ps[row * PPs + col]           = s[mt][nt][0] * scale + ms0;
                Ps[row * PPs + col + 1]       = s[mt][nt][1] * scale + ms1;
                Ps[(row + 8) * PPs + col]     = s[mt][nt][2] * scale + ms0;
                Ps[(row + 8) * PPs + col + 1] = s[mt][nt][3] * scale + ms1;
            }
        }
        __syncthreads();

        // ---- online softmax (2 threads per row) ----
        {
            float* rp = &Ps[sr * PPs + sh * 64];
            float mx = -INFINITY;
            #pragma unroll
            for (int j = 0; j < 16; j++) {
                float4 v = *(const float4*)(rp + j * 4);
                mx = fmaxf(mx, fmaxf(fmaxf(v.x, v.y), fmaxf(v.z, v.w)));
            }
            mx = fmaxf(mx, __shfl_xor_sync(0xffffffffu, mx, 1));
            float m_new = fmaxf(m_run, mx);
            float alpha = __expf(m_run - m_new);
            float sum = 0.f;
            #pragma unroll
            for (int j = 0; j < 16; j++) {
                float4 v = *(const float4*)(rp + j * 4);
                v.x = __expf(v.x - m_new); v.y = __expf(v.y - m_new);
                v.z = __expf(v.z - m_new); v.w = __expf(v.w - m_new);
                sum += v.x + v.y + v.z + v.w;
                v.x = tf32r(v.x); v.y = tf32r(v.y); v.z = tf32r(v.z); v.w = tf32r(v.w);
                *(float4*)(rp + j * 4) = v;
            }
            sum += __shfl_xor_sync(0xffffffffu, sum, 1);
            l_run = l_run * alpha + sum;
            m_run = m_new;
            if (sh == 0) sAlpha[sr] = alpha;
        }
        __syncthreads();

        // ---- O = O*alpha + P @ V (warp tile 64 q x 16 d) ----
        #pragma unroll
        for (int mt = 0; mt < 4; mt++) {
            int row = wm * 64 + mt * 16 + gid;
            float a0 = sAlpha[row], a1 = sAlpha[row + 8];
            #pragma unroll
            for (int nt = 0; nt < 2; nt++) {
                o[mt][nt][0] *= a0; o[mt][nt][1] *= a0;
                o[mt][nt][2] *= a1; o[mt][nt][3] *= a1;
            }
        }
        #pragma unroll
        for (int kk = 0; kk < 16; kk++) {
            const int k0 = kk * 8;
            uint32_t af[4][4], bf[2][2];
            #pragma unroll
            for (int mt = 0; mt < 4; mt++) {
                int row = wm * 64 + mt * 16 + gid;
                af[mt][0] = fb(Ps[row * PPs + k0 + tig]);
                af[mt][1] = fb(Ps[(row + 8) * PPs + k0 + tig]);
                af[mt][2] = fb(Ps[row * PPs + k0 + tig + 4]);
                af[mt][3] = fb(Ps[(row + 8) * PPs + k0 + tig + 4]);
            }
            #pragma unroll
            for (int nt = 0; nt < 2; nt++) {
                int d = wn * 16 + nt * 8 + gid;
                bf[nt][0] = fb(Vs[(k0 + tig) * PVs + d]);
                bf[nt][1] = fb(Vs[(k0 + tig + 4) * PVs + d]);
            }
            #pragma unroll
            for (int mt = 0; mt < 4; mt++)
                #pragma unroll
                for (int nt = 0; nt < 2; nt++)
                    mma8(o[mt][nt], af[mt][0], af[mt][1], af[mt][2], af[mt][3],
                         bf[nt][0], bf[nt][1]);
        }
        __syncthreads();
    }

    // final normalize + store
    if (sh == 0) sAlpha[sr] = 1.f / l_run;
    __syncthreads();
    #pragma unroll
    for (int mt = 0; mt < 4; mt++) {
        int row = wm * 64 + mt * 16 + gid;
        float i0 = sAlpha[row], i1 = sAlpha[row + 8];
        #pragma unroll
        for (int nt = 0; nt < 2; nt++) {
            int col = wn * 16 + nt * 8 + tig * 2;
            float* C0 = C + ((size_t)(b * Sv + q0 + row)) * Ev + h * 64 + col;
            float* C1 = C + ((size_t)(b * Sv + q0 + row + 8)) * Ev + h * 64 + col;
            *(float2*)C0 = make_float2(o[mt][nt][0] * i0, o[mt][nt][1] * i0);
            *(float2*)C1 = make_float2(o[mt][nt][2] * i1, o[mt][nt][3] * i1);
        }
    }
}

// ---------------------------------------------------------------------------
// LayerNorm(main_out + x) * gamma + beta.  One block per row, 256 threads.
// ---------------------------------------------------------------------------
__global__ __launch_bounds__(256) void ln_kernel(const float* __restrict__ MO,
                                                 const float* __restrict__ X,
                                                 const float* __restrict__ gamma,
                                                 const float* __restrict__ beta,
                                                 float* __restrict__ out) {
    const int r = blockIdx.x;
    const float* mo = MO + (size_t)r * Ev;
    const float* xr = X + (size_t)r * Ev;

    float v[4];
    float s1 = 0.f, s2 = 0.f;
    #pragma unroll
    for (int i = 0; i < 4; i++) {
        int idx = threadIdx.x + i * 256;
        v[i] = mo[idx] + xr[idx];
        s1 += v[i];
        s2 += v[i] * v[i];
    }
    #pragma unroll
    for (int o = 16; o > 0; o >>= 1) {
        s1 += __shfl_xor_sync(0xffffffffu, s1, o);
        s2 += __shfl_xor_sync(0xffffffffu, s2, o);
    }
    __shared__ float sh1[8], sh2[8], stats[2];
    const int w = threadIdx.x >> 5, lane = threadIdx.x & 31;
    if (lane == 0) { sh1[w] = s1; sh2[w] = s2; }
    __syncthreads();
    if (threadIdx.x == 0) {
        float t1 = 0.f, t2 = 0.f;
        #pragma unroll
        for (int i = 0; i < 8; i++) { t1 += sh1[i]; t2 += sh2[i]; }
        float mu = t1 * (1.f / Ev);
        float var = t2 * (1.f / Ev) - mu * mu;
        stats[0] = mu;
        stats[1] = rsqrtf(var + 1e-6f);
    }
    __syncthreads();
    const float mu = stats[0], rstd = stats[1];
    #pragma unroll
    for (int i = 0; i < 4; i++) {
        int idx = threadIdx.x + i * 256;
        out[(size_t)r * Ev + idx] = gamma[idx] * (v[i] - mu) * rstd + beta[idx];
    }
}

// ---------------------------------------------------------------------------
extern "C" void kernel_launch(void* const* d_in, const int* in_sizes, int n_in,
                              void* d_out, int out_size) {
    const float* x     = (const float*)d_in[0];
    const float* mask  = (const float*)d_in[1];
    const float* Wq    = (const float*)d_in[2];
    const float* bq    = (const float*)d_in[3];
    const float* Wk    = (const float*)d_in[4];
    const float* bk    = (const float*)d_in[5];
    const float* Wv    = (const float*)d_in[6];
    const float* bv    = (const float*)d_in[7];
    const float* Wo    = (const float*)d_in[8];
    const float* bo    = (const float*)d_in[9];
    const float* gamma = (const float*)d_in[10];
    const float* beta  = (const float*)d_in[11];
    float* out = (float*)d_out;

    float *Qb, *Kb, *Vb, *Cb, *Ob;
    cudaGetSymbolAddress((void**)&Qb, g_Q);
    cudaGetSymbolAddress((void**)&Kb, g_K);
    cudaGetSymbolAddress((void**)&Vb, g_V);
    cudaGetSymbolAddress((void**)&Cb, g_C);
    cudaGetSymbolAddress((void**)&Ob, g_O);

    cudaFuncSetAttribute(attn_tc, cudaFuncAttributeMaxDynamicSharedMemorySize, ATTN_SMEM);

    dim3 gg(8, 64);   // (N/128, M/128)
    gemm_tc<<<gg, 256>>>(x, Wq, bq, Qb);
    gemm_tc<<<gg, 256>>>(x, Wk, bk, Kb);
    gemm_tc<<<gg, 256>>>(x, Wv, bv, Vb);

    attn_tc<<<dim3(Sv / 128, Bv * Hv), 256, ATTN_SMEM>>>(Qb, Kb, Vb, mask, Cb);

    gemm_tc<<<gg, 256>>>(Cb, Wo, bo, Ob);

    ln_kernel<<<BS, 256>>>(Ob, x, gamma, beta, out);
}

// round 7
// speedup vs baseline: 4.1321x; 1.0733x over previous
#include <cuda_runtime.h>
#include <cstdint>
#include <math.h>

constexpr int Bv = 4, Sv = 2048, Ev = 1024, Hv = 16, Dv = 64;
constexpr int BSz = Bv * Sv;   // 8192

// Scratch (__device__ globals; no allocation)
__device__ float g_X[BSz * Ev];          // tf32-rounded x
__device__ float g_Q[BSz * Ev];
__device__ float g_K[BSz * Ev];
__device__ float g_V[BSz * Ev];
__device__ float g_VT[BSz * Ev];         // V transposed per (b,h): [bh][d][s]
__device__ float g_C[BSz * Ev];          // attn context (tf32-rounded)
__device__ float g_O[BSz * Ev];          // main_out
__device__ float g_WT[4ull * Ev * Ev];   // transposed+rounded weights

// ---------------------------------------------------------------------------
// helpers
// ---------------------------------------------------------------------------
__device__ __forceinline__ float tf32r(float f) {
    uint32_t r;
    asm("cvt.rna.tf32.f32 %0, %1;" : "=r"(r) : "f"(f));
    return __uint_as_float(r);
}
__device__ __forceinline__ uint32_t smem_u32(const void* p) {
    uint32_t a;
    asm("{ .reg .u64 t; cvta.to.shared.u64 t, %1; cvt.u32.u64 %0, t; }" : "=r"(a) : "l"(p));
    return a;
}
__device__ __forceinline__ void mma8(float* d, const uint32_t* a, uint32_t b0, uint32_t b1) {
    asm volatile(
        "mma.sync.aligned.m16n8k8.row.col.f32.tf32.tf32.f32 "
        "{%0,%1,%2,%3}, {%4,%5,%6,%7}, {%8,%9}, {%0,%1,%2,%3};"
        : "+f"(d[0]), "+f"(d[1]), "+f"(d[2]), "+f"(d[3])
        : "r"(a[0]), "r"(a[1]), "r"(a[2]), "r"(a[3]), "r"(b0), "r"(b1));
}
__device__ __forceinline__ void ldsm4(uint32_t* r, uint32_t addr) {
    asm volatile("ldmatrix.sync.aligned.m8n8.x4.shared.b16 {%0,%1,%2,%3}, [%4];"
                 : "=r"(r[0]), "=r"(r[1]), "=r"(r[2]), "=r"(r[3]) : "r"(addr));
}
__device__ __forceinline__ void cpa16(uint32_t dst, const void* src) {
    asm volatile("cp.async.cg.shared.global [%0], [%1], 16;" :: "r"(dst), "l"(src));
}
#define CP_COMMIT() asm volatile("cp.async.commit_group;" ::: "memory")
#define CP_WAIT(n)  asm volatile("cp.async.wait_group %0;" :: "n"(n) : "memory")

// ---------------------------------------------------------------------------
// prep kernels: tf32 rounding / transposes
// ---------------------------------------------------------------------------
__global__ void round_x(const float* __restrict__ in, float* __restrict__ out) {
    size_t i = ((size_t)blockIdx.x * 256 + threadIdx.x) * 4;
    float4 v = *(const float4*)(in + i);
    v.x = tf32r(v.x); v.y = tf32r(v.y); v.z = tf32r(v.z); v.w = tf32r(v.w);
    *(float4*)(out + i) = v;
}

// WT[n][k] = round(W[k][n])
__global__ void trW(const float* __restrict__ in, float* __restrict__ out) {
    __shared__ float t[32][33];
    int k0 = blockIdx.y * 32, n0 = blockIdx.x * 32;
    for (int i = threadIdx.y; i < 32; i += 8)
        t[i][threadIdx.x] = in[(size_t)(k0 + i) * 1024 + n0 + threadIdx.x];
    __syncthreads();
    for (int i = threadIdx.y; i < 32; i += 8)
        out[(size_t)(n0 + i) * 1024 + k0 + threadIdx.x] = tf32r(t[threadIdx.x][i]);
}

// VT[bh][d][s] = V[b][s][h*64+d]  (V already rounded)
__global__ void trV(const float* __restrict__ in, float* __restrict__ out) {
    __shared__ float t[32][33];
    int bh = blockIdx.z, b = bh >> 4, h = bh & 15;
    int s0 = blockIdx.x * 32, d0 = blockIdx.y * 32;
    const float* ip = in + ((size_t)b * Sv) * Ev + h * 64;
    for (int i = threadIdx.y; i < 32; i += 8)
        t[i][threadIdx.x] = ip[(size_t)(s0 + i) * Ev + d0 + threadIdx.x];
    __syncthreads();
    float* op = out + ((size_t)bh * 64) * Sv;
    for (int i = threadIdx.y; i < 32; i += 8)
        op[(size_t)(d0 + i) * Sv + s0 + threadIdx.x] = t[threadIdx.x][i];
}

// ---------------------------------------------------------------------------
// GEMM: C[8192,1024] = A @ WT^T + bias.  512 thr, warp grid 4x4, tile 128x128,
// K-chunk 32, 3-stage cp.async pipeline, ldmatrix fragments.
// ---------------------------------------------------------------------------
constexpr int GP = 36;                     // smem pitch (floats), banks 4*r+c
constexpr int G_STAGE = 2 * 128 * GP;      // floats per stage (A + B panels)
constexpr int GEMM_SMEM = 3 * G_STAGE * 4; // 110592 B

template <bool RND>
__global__ __launch_bounds__(512) void gemm_tc(const float* __restrict__ A,
                                               const float* __restrict__ WT,
                                               const float* __restrict__ bias,
                                               float* __restrict__ C) {
    extern __shared__ float sm[];
    const int tid = threadIdx.x, wid = tid >> 5, lane = tid & 31;
    const int gid = lane >> 2, tig = lane & 3;
    const int wm = wid >> 2, wn = wid & 3;
    const int m0 = blockIdx.y * 128, n0 = blockIdx.x * 128;
    const uint32_t smb = smem_u32(sm);
    const int rsA = (lane & 7) + ((lane >> 3) & 1) * 8, csA = (lane >> 4) & 1;
    const int rsB = (lane & 7) + ((lane >> 4) & 1) * 8, csB = (lane >> 3) & 1;

    const int r0 = tid >> 3, u0 = tid & 7;
    const int r1 = (tid + 512) >> 3, u1 = (tid + 512) & 7;

    auto issue = [&](int c) {
        uint32_t dA = smb + (uint32_t)((c % 3) * G_STAGE) * 4;
        uint32_t dB = dA + 128 * GP * 4;
        const float* pa = A  + (size_t)m0 * 1024 + c * 32;
        const float* pb = WT + (size_t)n0 * 1024 + c * 32;
        cpa16(dA + r0 * GP * 4 + u0 * 16, pa + (size_t)r0 * 1024 + u0 * 4);
        cpa16(dA + r1 * GP * 4 + u1 * 16, pa + (size_t)r1 * 1024 + u1 * 4);
        cpa16(dB + r0 * GP * 4 + u0 * 16, pb + (size_t)r0 * 1024 + u0 * 4);
        cpa16(dB + r1 * GP * 4 + u1 * 16, pb + (size_t)r1 * 1024 + u1 * 4);
    };

    float acc[2][4][4] = {};
    issue(0); CP_COMMIT();
    issue(1); CP_COMMIT();

    for (int c = 0; c < 32; c++) {
        CP_WAIT(1);
        __syncthreads();
        if (c + 2 < 32) { issue(c + 2); CP_COMMIT(); }
        uint32_t bA = smb + (uint32_t)((c % 3) * G_STAGE) * 4;
        uint32_t bB = bA + 128 * GP * 4;
        uint32_t aB0 = bA + (uint32_t)((wm * 32 + rsA) * GP + csA * 4) * 4;
        uint32_t aB1 = aB0 + 16 * GP * 4;
        uint32_t bB0 = bB + (uint32_t)((wn * 32 + rsB) * GP + csB * 4) * 4;
        uint32_t bB1 = bB0 + 16 * GP * 4;
        #pragma unroll
        for (int kk = 0; kk < 4; kk++) {
            uint32_t a[2][4], bb[2][4];
            ldsm4(a[0], aB0 + kk * 32);
            ldsm4(a[1], aB1 + kk * 32);
            ldsm4(bb[0], bB0 + kk * 32);
            ldsm4(bb[1], bB1 + kk * 32);
            #pragma unroll
            for (int mt = 0; mt < 2; mt++)
                #pragma unroll
                for (int nt = 0; nt < 4; nt++)
                    mma8(acc[mt][nt], a[mt], bb[nt >> 1][(nt & 1) * 2],
                         bb[nt >> 1][(nt & 1) * 2 + 1]);
        }
    }

    #pragma unroll
    for (int mt = 0; mt < 2; mt++) {
        int row = m0 + wm * 32 + mt * 16 + gid;
        #pragma unroll
        for (int nt = 0; nt < 4; nt++) {
            int col = n0 + wn * 32 + nt * 8 + tig * 2;
            float b0 = bias[col], b1 = bias[col + 1];
            float v0 = acc[mt][nt][0] + b0, v1 = acc[mt][nt][1] + b1;
            float v2 = acc[mt][nt][2] + b0, v3 = acc[mt][nt][3] + b1;
            if (RND) { v0 = tf32r(v0); v1 = tf32r(v1); v2 = tf32r(v2); v3 = tf32r(v3); }
            *(float2*)(C + (size_t)row * 1024 + col) = make_float2(v0, v1);
            *(float2*)(C + (size_t)(row + 8) * 1024 + col) = make_float2(v2, v3);
        }
    }
}

// ---------------------------------------------------------------------------
// Flash attention, 512 threads, ldmatrix fragments, cp.async prefetch.
// Per CTA: 128 queries, 16 key tiles of 128. S warp tile 32x32; PV 32x16.
// smem (floats): Qs[128x68] Ks[128x68] Vs[2][64x132] Ps[128x132] mask[128] alpha[128]
// ---------------------------------------------------------------------------
constexpr int PQ = 68, PW = 132;
constexpr int OFF_K  = 128 * PQ;            // 8704
constexpr int OFF_V  = OFF_K + 128 * PQ;    // 17408
constexpr int VBUF   = 64 * PW;             // 8448
constexpr int OFF_P  = OFF_V + 2 * VBUF;    // 34304
constexpr int OFF_MS = OFF_P + 128 * PW;    // 51200
constexpr int OFF_AL = OFF_MS + 128;        // 51328
constexpr int ATTN_SMEM = (OFF_AL + 128) * 4;  // 205824 B

__global__ __launch_bounds__(512) void attn_tc(const float* __restrict__ Q,
                                               const float* __restrict__ Kg,
                                               const float* __restrict__ VT,
                                               const float* __restrict__ mask,
                                               float* __restrict__ C) {
    extern __shared__ float sm[];
    const int tid = threadIdx.x, wid = tid >> 5, lane = tid & 31;
    const int gid = lane >> 2, tig = lane & 3;
    const int wm = wid >> 2, wn = wid & 3;
    const int b = blockIdx.y >> 4;
    const int q0 = blockIdx.x * 128;
    const uint32_t smb = smem_u32(sm);
    const int rsA = (lane & 7) + ((lane >> 3) & 1) * 8, csA = (lane >> 4) & 1;
    const int rsB = (lane & 7) + ((lane >> 4) & 1) * 8, csB = (lane >> 3) & 1;
    const int sr = tid >> 2, part = tid & 3;
    const float scale = 0.03125f;   // 1/sqrt(1024)

    const float* Qg  = Q  + ((size_t)(b * Sv + q0)) * Ev + (blockIdx.y & 15) * 64;
    const float* Kgp = Kg + ((size_t)b * Sv) * Ev + (blockIdx.y & 15) * 64;
    const float* VTp = VT + ((size_t)blockIdx.y * 64) * Sv;

    auto issueK = [&](int t) {
        const float* p = Kgp + (size_t)(t * 128) * Ev;
        #pragma unroll
        for (int i = 0; i < 4; i++) {
            int unit = tid + i * 512, r = unit >> 4, u = unit & 15;
            cpa16(smb + (uint32_t)(OFF_K + r * PQ + u * 4) * 4, p + (size_t)r * Ev + u * 4);
        }
    };
    auto issueV = [&](int t) {
        uint32_t dst = smb + (uint32_t)(OFF_V + (t & 1) * VBUF) * 4;
        #pragma unroll
        for (int i = 0; i < 4; i++) {
            int unit = tid + i * 512, d = unit >> 5, u = unit & 31;
            cpa16(dst + (uint32_t)(d * PW + u * 4) * 4, VTp + (size_t)d * Sv + t * 128 + u * 4);
        }
    };
    auto issueM = [&](int t) {
        if (tid < 32)
            cpa16(smb + (uint32_t)(OFF_MS + tid * 4) * 4, mask + (size_t)b * Sv + t * 128 + tid * 4);
    };

    // prologue: Q + tile 0
    #pragma unroll
    for (int i = 0; i < 4; i++) {
        int unit = tid + i * 512, r = unit >> 4, u = unit & 15;
        cpa16(smb + (uint32_t)(r * PQ + u * 4) * 4, Qg + (size_t)r * Ev + u * 4);
    }
    issueK(0); issueV(0); issueM(0);
    CP_COMMIT();

    float o[2][2][4] = {};
    float m_run = -INFINITY, l_run = 0.f;

    for (int t = 0; t < 16; t++) {
        CP_WAIT(0);
        __syncthreads();

        // ---- S = Q @ K^T ----
        float s[2][4][4] = {};
        {
            uint32_t aB0 = smb + (uint32_t)((wm * 32 + rsA) * PQ + csA * 4) * 4;
            uint32_t aB1 = aB0 + 16 * PQ * 4;
            uint32_t bB0 = smb + (uint32_t)(OFF_K + (wn * 32 + rsB) * PQ + csB * 4) * 4;
            uint32_t bB1 = bB0 + 16 * PQ * 4;
            #pragma unroll
            for (int kk = 0; kk < 8; kk++) {
                uint32_t a[2][4], bb[2][4];
                ldsm4(a[0], aB0 + kk * 32);
                ldsm4(a[1], aB1 + kk * 32);
                ldsm4(bb[0], bB0 + kk * 32);
                ldsm4(bb[1], bB1 + kk * 32);
                #pragma unroll
                for (int mt = 0; mt < 2; mt++)
                    #pragma unroll
                    for (int nt = 0; nt < 4; nt++)
                        mma8(s[mt][nt], a[mt], bb[nt >> 1][(nt & 1) * 2],
                             bb[nt >> 1][(nt & 1) * 2 + 1]);
            }
        }
        // store scaled+masked P
        {
            const float* msp = sm + OFF_MS;
            #pragma unroll
            for (int mt = 0; mt < 2; mt++) {
                int row = wm * 32 + mt * 16 + gid;
                #pragma unroll
                for (int nt = 0; nt < 4; nt++) {
                    int col = wn * 32 + nt * 8 + tig * 2;
                    float mv0 = msp[col] * (-1e9f), mv1 = msp[col + 1] * (-1e9f);
                    *(float2*)(sm + OFF_P + row * PW + col) =
                        make_float2(s[mt][nt][0] * scale + mv0, s[mt][nt][1] * scale + mv1);
                    *(float2*)(sm + OFF_P + (row + 8) * PW + col) =
                        make_float2(s[mt][nt][2] * scale + mv0, s[mt][nt][3] * scale + mv1);
                }
            }
        }
        __syncthreads();
        if (t + 1 < 16) { issueK(t + 1); issueV(t + 1); issueM(t + 1); CP_COMMIT(); }

        // ---- online softmax (4 threads per row) ----
        float alpha;
        {
            float* rp = sm + OFF_P + sr * PW + part * 32;
            float mx = -INFINITY;
            #pragma unroll
            for (int j = 0; j < 8; j++) {
                float4 v = *(const float4*)(rp + j * 4);
                mx = fmaxf(mx, fmaxf(fmaxf(v.x, v.y), fmaxf(v.z, v.w)));
            }
            mx = fmaxf(mx, __shfl_xor_sync(0xffffffffu, mx, 1));
            mx = fmaxf(mx, __shfl_xor_sync(0xffffffffu, mx, 2));
            float m_new = fmaxf(m_run, mx);
            alpha = __expf(m_run - m_new);
            float sum = 0.f;
            #pragma unroll
            for (int j = 0; j < 8; j++) {
                float4 v = *(const float4*)(rp + j * 4);
                v.x = __expf(v.x - m_new); v.y = __expf(v.y - m_new);
                v.z = __expf(v.z - m_new); v.w = __expf(v.w - m_new);
                sum += v.x + v.y + v.z + v.w;
                v.x = tf32r(v.x); v.y = tf32r(v.y); v.z = tf32r(v.z); v.w = tf32r(v.w);
                *(float4*)(rp + j * 4) = v;
            }
            sum += __shfl_xor_sync(0xffffffffu, sum, 1);
            sum += __shfl_xor_sync(0xffffffffu, sum, 2);
            l_run = l_run * alpha + sum;
            m_run = m_new;
            if (part == 0) sm[OFF_AL + sr] = alpha;
        }
        __syncthreads();

        // ---- O = O*alpha + P @ V ----
        #pragma unroll
        for (int mt = 0; mt < 2; mt++) {
            int row = wm * 32 + mt * 16 + gid;
            float a0 = sm[OFF_AL + row], a1 = sm[OFF_AL + row + 8];
            #pragma unroll
            for (int nt = 0; nt < 2; nt++) {
                o[mt][nt][0] *= a0; o[mt][nt][1] *= a0;
                o[mt][nt][2] *= a1; o[mt][nt][3] *= a1;
            }
        }
        {
            uint32_t aB0 = smb + (uint32_t)(OFF_P + (wm * 32 + rsA) * PW + csA * 4) * 4;
            uint32_t aB1 = aB0 + 16 * PW * 4;
            uint32_t vB  = smb + (uint32_t)(OFF_V + (t & 1) * VBUF + (wn * 16 + rsB) * PW + csB * 4) * 4;
            #pragma unroll
            for (int kk = 0; kk < 16; kk++) {
                uint32_t a[2][4], bb[4];
                ldsm4(a[0], aB0 + kk * 32);
                ldsm4(a[1], aB1 + kk * 32);
                ldsm4(bb, vB + kk * 32);
                #pragma unroll
                for (int mt = 0; mt < 2; mt++) {
                    mma8(o[mt][0], a[mt], bb[0], bb[1]);
                    mma8(o[mt][1], a[mt], bb[2], bb[3]);
                }
            }
        }
        // next loop-top __syncthreads protects Ps/Ks reuse
    }

    // epilogue
    if (part == 0) sm[OFF_AL + sr] = 1.f / l_run;
    __syncthreads();
    #pragma unroll
    for (int mt = 0; mt < 2; mt++) {
        int row = wm * 32 + mt * 16 + gid;
        float i0 = sm[OFF_AL + row], i1 = sm[OFF_AL + row + 8];
        #pragma unroll
        for (int nt = 0; nt < 2; nt++) {
            int col = (blockIdx.y & 15) * 64 + wn * 16 + nt * 8 + tig * 2;
            float* C0 = C + ((size_t)(b * Sv + q0 + row)) * Ev + col;
            float* C1 = C + ((size_t)(b * Sv + q0 + row + 8)) * Ev + col;
            *(float2*)C0 = make_float2(tf32r(o[mt][nt][0] * i0), tf32r(o[mt][nt][1] * i0));
            *(float2*)C1 = make_float2(tf32r(o[mt][nt][2] * i1), tf32r(o[mt][nt][3] * i1));
        }
    }
}

// ---------------------------------------------------------------------------
// LayerNorm(main_out + x)
// ---------------------------------------------------------------------------
__global__ __launch_bounds__(256) void ln_kernel(const float* __restrict__ MO,
                                                 const float* __restrict__ X,
                                                 const float* __restrict__ gamma,
                                                 const float* __restrict__ beta,
                                                 float* __restrict__ out) {
    const int r = blockIdx.x;
    const float* mo = MO + (size_t)r * Ev;
    const float* xr = X + (size_t)r * Ev;

    float v[4];
    float s1 = 0.f, s2 = 0.f;
    #pragma unroll
    for (int i = 0; i < 4; i++) {
        int idx = threadIdx.x + i * 256;
        v[i] = mo[idx] + xr[idx];
        s1 += v[i];
        s2 += v[i] * v[i];
    }
    #pragma unroll
    for (int o = 16; o > 0; o >>= 1) {
        s1 += __shfl_xor_sync(0xffffffffu, s1, o);
        s2 += __shfl_xor_sync(0xffffffffu, s2, o);
    }
    __shared__ float sh1[8], sh2[8], stats[2];
    const int w = threadIdx.x >> 5, lane = threadIdx.x & 31;
    if (lane == 0) { sh1[w] = s1; sh2[w] = s2; }
    __syncthreads();
    if (threadIdx.x == 0) {
        float t1 = 0.f, t2 = 0.f;
        #pragma unroll
        for (int i = 0; i < 8; i++) { t1 += sh1[i]; t2 += sh2[i]; }
        float mu = t1 * (1.f / Ev);
        float var = t2 * (1.f / Ev) - mu * mu;
        stats[0] = mu;
        stats[1] = rsqrtf(var + 1e-6f);
    }
    __syncthreads();
    const float mu = stats[0], rstd = stats[1];
    #pragma unroll
    for (int i = 0; i < 4; i++) {
        int idx = threadIdx.x + i * 256;
        out[(size_t)r * Ev + idx] = gamma[idx] * (v[i] - mu) * rstd + beta[idx];
    }
}

// ---------------------------------------------------------------------------
extern "C" void kernel_launch(void* const* d_in, const int* in_sizes, int n_in,
                              void* d_out, int out_size) {
    const float* x     = (const float*)d_in[0];
    const float* mask  = (const float*)d_in[1];
    const float* Wq    = (const float*)d_in[2];
    const float* bq    = (const float*)d_in[3];
    const float* Wk    = (const float*)d_in[4];
    const float* bk    = (const float*)d_in[5];
    const float* Wv    = (const float*)d_in[6];
    const float* bv    = (const float*)d_in[7];
    const float* Wo    = (const float*)d_in[8];
    const float* bo    = (const float*)d_in[9];
    const float* gamma = (const float*)d_in[10];
    const float* beta  = (const float*)d_in[11];
    float* out = (float*)d_out;

    float *Xb, *Qb, *Kb, *Vb, *VTb, *Cb, *Ob, *WT;
    cudaGetSymbolAddress((void**)&Xb, g_X);
    cudaGetSymbolAddress((void**)&Qb, g_Q);
    cudaGetSymbolAddress((void**)&Kb, g_K);
    cudaGetSymbolAddress((void**)&Vb, g_V);
    cudaGetSymbolAddress((void**)&VTb, g_VT);
    cudaGetSymbolAddress((void**)&Cb, g_C);
    cudaGetSymbolAddress((void**)&Ob, g_O);
    cudaGetSymbolAddress((void**)&WT, g_WT);
    float* WTq = WT;
    float* WTk = WT + 1ull * Ev * Ev;
    float* WTv = WT + 2ull * Ev * Ev;
    float* WTo = WT + 3ull * Ev * Ev;

    cudaFuncSetAttribute(gemm_tc<true>,  cudaFuncAttributeMaxDynamicSharedMemorySize, GEMM_SMEM);
    cudaFuncSetAttribute(gemm_tc<false>, cudaFuncAttributeMaxDynamicSharedMemorySize, GEMM_SMEM);
    cudaFuncSetAttribute(attn_tc, cudaFuncAttributeMaxDynamicSharedMemorySize, ATTN_SMEM);

    // prep: round x, transpose+round weights
    round_x<<<BSz * Ev / 1024, 256>>>(x, Xb);
    dim3 tg(32, 32), tb(32, 8);
    trW<<<tg, tb>>>(Wq, WTq);
    trW<<<tg, tb>>>(Wk, WTk);
    trW<<<tg, tb>>>(Wv, WTv);
    trW<<<tg, tb>>>(Wo, WTo);

    dim3 gg(8, 64);
    gemm_tc<true><<<gg, 512, GEMM_SMEM>>>(Xb, WTq, bq, Qb);
    gemm_tc<true><<<gg, 512, GEMM_SMEM>>>(Xb, WTk, bk, Kb);
    gemm_tc<true><<<gg, 512, GEMM_SMEM>>>(Xb, WTv, bv, Vb);

    trV<<<dim3(Sv / 32, 2, Bv * Hv), tb>>>(Vb, VTb);

    attn_tc<<<dim3(Sv / 128, Bv * Hv), 512, ATTN_SMEM>>>(Qb, Kb, VTb, mask, Cb);

    gemm_tc<false><<<gg, 512, GEMM_SMEM>>>(Cb, WTo, bo, Ob);

    ln_kernel<<<BSz, 256>>>(Ob, x, gamma, beta, out);
}

// round 9
// speedup vs baseline: 8.1876x; 1.9815x over previous
#include <cuda_runtime.h>
#include <cuda_fp16.h>
#include <cstdint>
#include <math.h>

constexpr int Bv = 4, Sv = 2048, Ev = 1024, Hv = 16;
constexpr int BSz = Bv * Sv;   // 8192

// Scratch (__device__ globals; no allocation)
__device__ __half g_Xh[BSz * Ev];         // fp16 x
__device__ __half g_Qh[BSz * Ev];         // fp16 Q, pre-scaled by 1/32
__device__ __half g_Kh[BSz * Ev];
__device__ __half g_Vh[BSz * Ev];
__device__ __half g_Ch[BSz * Ev];         // fp16 attention context
__device__ float  g_O[BSz * Ev];          // main_out (fp32, for LN)
__device__ __half g_WT[4ull * Ev * Ev];   // fp16 transposed weights [n][k]

// ---------------------------------------------------------------------------
// helpers
// ---------------------------------------------------------------------------
__device__ __forceinline__ uint32_t smem_u32(const void* p) {
    uint32_t a;
    asm("{ .reg .u64 t; cvta.to.shared.u64 t, %1; cvt.u32.u64 %0, t; }" : "=r"(a) : "l"(p));
    return a;
}
// D += A(16x16) * B(16x8), fp16 in, fp32 accum
__device__ __forceinline__ void mma16(float* d, const uint32_t* a, uint32_t b0, uint32_t b1) {
    asm volatile(
        "mma.sync.aligned.m16n8k16.row.col.f32.f16.f16.f32 "
        "{%0,%1,%2,%3}, {%4,%5,%6,%7}, {%8,%9}, {%0,%1,%2,%3};"
        : "+f"(d[0]), "+f"(d[1]), "+f"(d[2]), "+f"(d[3])
        : "r"(a[0]), "r"(a[1]), "r"(a[2]), "r"(a[3]), "r"(b0), "r"(b1));
}
__device__ __forceinline__ void ldsm4(uint32_t* r, uint32_t addr) {
    asm volatile("ldmatrix.sync.aligned.m8n8.x4.shared.b16 {%0,%1,%2,%3}, [%4];"
                 : "=r"(r[0]), "=r"(r[1]), "=r"(r[2]), "=r"(r[3]) : "r"(addr));
}
__device__ __forceinline__ void ldsm4t(uint32_t* r, uint32_t addr) {
    asm volatile("ldmatrix.sync.aligned.m8n8.x4.trans.shared.b16 {%0,%1,%2,%3}, [%4];"
                 : "=r"(r[0]), "=r"(r[1]), "=r"(r[2]), "=r"(r[3]) : "r"(addr));
}
__device__ __forceinline__ void cpa16(uint32_t dst, const void* src) {
    asm volatile("cp.async.cg.shared.global [%0], [%1], 16;" :: "r"(dst), "l"(src));
}
#define CP_COMMIT() asm volatile("cp.async.commit_group;" ::: "memory")
#define CP_WAIT(n)  asm volatile("cp.async.wait_group %0;" :: "n"(n) : "memory")
__device__ __forceinline__ uint32_t h2u(__half2 h) { return *(uint32_t*)&h; }

// ---------------------------------------------------------------------------
// prep: fp32 -> fp16 convert / transpose-convert
// ---------------------------------------------------------------------------
__global__ void cvtX(const float* __restrict__ in, __half* __restrict__ out) {
    size_t i = ((size_t)blockIdx.x * 256 + threadIdx.x) * 4;
    float4 v = *(const float4*)(in + i);
    __half2* o = (__half2*)(out + i);
    o[0] = __floats2half2_rn(v.x, v.y);
    o[1] = __floats2half2_rn(v.z, v.w);
}
// WT[n][k] = half(W[k][n])
__global__ void cvtW(const float* __restrict__ in, __half* __restrict__ out) {
    __shared__ float t[32][33];
    int k0 = blockIdx.y * 32, n0 = blockIdx.x * 32;
    for (int i = threadIdx.y; i < 32; i += 8)
        t[i][threadIdx.x] = in[(size_t)(k0 + i) * 1024 + n0 + threadIdx.x];
    __syncthreads();
    for (int i = threadIdx.y; i < 32; i += 8)
        out[(size_t)(n0 + i) * 1024 + k0 + threadIdx.x] = __float2half(t[threadIdx.x][i]);
}

// ---------------------------------------------------------------------------
// fp16 GEMM: C[8192,1024] = A @ WT^T + bias (optional *scale, fp16 or fp32 out)
// 512 thr, warp grid 4x4, CTA tile 128x128, K-chunk 64, 3-stage cp.async.
// smem pitch 72 halves (144B): ldmatrix conflict-free, rows 16B-aligned.
// ---------------------------------------------------------------------------
constexpr int GPH = 72;
constexpr int GSTB = 2 * 128 * GPH * 2;   // stage bytes (A+B panels) = 36864
constexpr int GEMM_SMEM = 3 * GSTB;       // 110592

template <bool HOUT>
__global__ __launch_bounds__(512) void gemm_h(const __half* __restrict__ A,
                                              const __half* __restrict__ WT,
                                              const float* __restrict__ bias,
                                              void* __restrict__ Cout, float scale) {
    extern __shared__ char sm[];
    const int tid = threadIdx.x, wid = tid >> 5, lane = tid & 31;
    const int gid = lane >> 2, tig = lane & 3;
    const int wm = wid >> 2, wn = wid & 3;
    const int m0 = blockIdx.y * 128, n0 = blockIdx.x * 128;
    const uint32_t smb = smem_u32(sm);
    const int rsA = lane & 15, csA = (lane >> 4) * 8;
    const int rsB = (lane & 7) + ((lane >> 4) & 1) * 8, csB = ((lane >> 3) & 1) * 8;

    auto issue = [&](int c) {
        uint32_t dA = smb + (uint32_t)((c % 3) * GSTB);
        uint32_t dB = dA + 128 * GPH * 2;
        const __half* pa = A  + (size_t)m0 * 1024 + c * 64;
        const __half* pb = WT + (size_t)n0 * 1024 + c * 64;
        #pragma unroll
        for (int i = 0; i < 2; i++) {
            int unit = tid + i * 512, r = unit >> 3, u = unit & 7;
            cpa16(dA + (uint32_t)(r * GPH + u * 8) * 2, pa + (size_t)r * 1024 + u * 8);
            cpa16(dB + (uint32_t)(r * GPH + u * 8) * 2, pb + (size_t)r * 1024 + u * 8);
        }
    };

    float acc[2][4][4] = {};
    issue(0); CP_COMMIT();
    issue(1); CP_COMMIT();

    for (int c = 0; c < 16; c++) {
        CP_WAIT(1);
        __syncthreads();
        if (c + 2 < 16) { issue(c + 2); CP_COMMIT(); }
        uint32_t bA = smb + (uint32_t)((c % 3) * GSTB);
        uint32_t aB0 = bA + (uint32_t)((wm * 32 + rsA) * GPH + csA) * 2;
        uint32_t aB1 = aB0 + 16 * GPH * 2;
        uint32_t bB0 = bA + 128 * GPH * 2 + (uint32_t)((wn * 32 + rsB) * GPH + csB) * 2;
        uint32_t bB1 = bB0 + 16 * GPH * 2;
        #pragma unroll
        for (int kk = 0; kk < 4; kk++) {
            uint32_t a[2][4], bb[2][4];
            ldsm4(a[0], aB0 + kk * 32);
            ldsm4(a[1], aB1 + kk * 32);
            ldsm4(bb[0], bB0 + kk * 32);
            ldsm4(bb[1], bB1 + kk * 32);
            #pragma unroll
            for (int mt = 0; mt < 2; mt++)
                #pragma unroll
                for (int nt = 0; nt < 4; nt++)
                    mma16(acc[mt][nt], a[mt], bb[nt >> 1][(nt & 1) * 2],
                          bb[nt >> 1][(nt & 1) * 2 + 1]);
        }
        __syncthreads();
    }

    #pragma unroll
    for (int mt = 0; mt < 2; mt++) {
        int row = m0 + wm * 32 + mt * 16 + gid;
        #pragma unroll
        for (int nt = 0; nt < 4; nt++) {
            int col = n0 + wn * 32 + nt * 8 + tig * 2;
            float b0 = bias[col], b1 = bias[col + 1];
            float v0 = (acc[mt][nt][0] + b0) * scale, v1 = (acc[mt][nt][1] + b1) * scale;
            float v2 = (acc[mt][nt][2] + b0) * scale, v3 = (acc[mt][nt][3] + b1) * scale;
            if (HOUT) {
                __half* C = (__half*)Cout;
                *(__half2*)(C + (size_t)row * 1024 + col) = __floats2half2_rn(v0, v1);
                *(__half2*)(C + (size_t)(row + 8) * 1024 + col) = __floats2half2_rn(v2, v3);
            } else {
                float* C = (float*)Cout;
                *(float2*)(C + (size_t)row * 1024 + col) = make_float2(v0, v1);
                *(float2*)(C + (size_t)(row + 8) * 1024 + col) = make_float2(v2, v3);
            }
        }
    }
}

// ---------------------------------------------------------------------------
// fp16 flash attention.  512 thr = 16 warps as 8(q) x 2(key-half).
// CTA: 128 queries; 16 key tiles of 128.  Warp: 16q x 64keys.
// S fragments stay in registers; P converted to fp16 A-fragments in regs
// (m16n8k16 C layout == A layout).  V via ldmatrix.trans (no transpose prep).
// smem: Qh[128x72] Kh[128x72] Vh[2][128x72] (halves), mask f32[128], red f32[2][256]
// ---------------------------------------------------------------------------
constexpr int OQ = 0, OK = 18432, OV = 36864, OVB = 18432;
constexpr int OM = 73728, ORM = 74240, ORS = 75264;
constexpr int ATTN_SMEM = 76288;

__global__ __launch_bounds__(512) void attn_h(const __half* __restrict__ Q,
                                              const __half* __restrict__ Kg,
                                              const __half* __restrict__ Vg,
                                              const float* __restrict__ mask,
                                              __half* __restrict__ C) {
    extern __shared__ char sm[];
    const int tid = threadIdx.x, wid = tid >> 5, lane = tid & 31;
    const int gid = lane >> 2, tig = lane & 3;
    const int wm = wid >> 1, wn = wid & 1;       // 8 x 2 warp grid
    const int b = blockIdx.y >> 4, h = blockIdx.y & 15;
    const int q0 = blockIdx.x * 128;
    const uint32_t smb = smem_u32(sm);
    const int rsA = lane & 15, csA = (lane >> 4) * 8;           // A / V-trans pattern
    const int rsB = (lane & 7) + ((lane >> 4) & 1) * 8;         // B (K) pattern
    const int csB = ((lane >> 3) & 1) * 8;

    const __half* Qg  = Q  + ((size_t)(b * Sv + q0)) * Ev + h * 64;
    const __half* Kgp = Kg + ((size_t)b * Sv) * Ev + h * 64;
    const __half* Vgp = Vg + ((size_t)b * Sv) * Ev + h * 64;

    auto issueK = [&](int t) {
        const __half* p = Kgp + (size_t)(t * 128) * Ev;
        #pragma unroll
        for (int i = 0; i < 2; i++) {
            int unit = tid + i * 512, r = unit >> 3, u = unit & 7;
            cpa16(smb + OK + (uint32_t)(r * GPH + u * 8) * 2, p + (size_t)r * Ev + u * 8);
        }
    };
    auto issueV = [&](int t) {
        const __half* p = Vgp + (size_t)(t * 128) * Ev;
        uint32_t dst = smb + OV + (t & 1) * OVB;
        #pragma unroll
        for (int i = 0; i < 2; i++) {
            int unit = tid + i * 512, r = unit >> 3, u = unit & 7;
            cpa16(dst + (uint32_t)(r * GPH + u * 8) * 2, p + (size_t)r * Ev + u * 8);
        }
    };
    auto issueM = [&](int t) {
        if (tid < 32)
            cpa16(smb + OM + tid * 16, mask + (size_t)b * Sv + t * 128 + tid * 4);
    };

    // prologue: Q + tile 0
    #pragma unroll
    for (int i = 0; i < 2; i++) {
        int unit = tid + i * 512, r = unit >> 3, u = unit & 7;
        cpa16(smb + OQ + (uint32_t)(r * GPH + u * 8) * 2, Qg + (size_t)r * Ev + u * 8);
    }
    issueK(0); issueV(0); issueM(0);
    CP_COMMIT();

    float o[8][4] = {};
    float m_run0 = -INFINITY, m_run1 = -INFINITY, l_run0 = 0.f, l_run1 = 0.f;
    float* sMask = (float*)(sm + OM);
    float* sRM = (float*)(sm + ORM);
    float* sRS = (float*)(sm + ORS);
    const int row0 = wm * 16 + gid, row1 = row0 + 8;

    for (int t = 0; t < 16; t++) {
        CP_WAIT(0);
        __syncthreads();

        // ---- S = Q @ K^T : warp computes 16q x 64keys ----
        float s[8][4] = {};
        {
            uint32_t aQ = smb + OQ + (uint32_t)((wm * 16 + rsA) * GPH + csA) * 2;
            uint32_t kB = smb + OK + (uint32_t)((wn * 64 + rsB) * GPH + csB) * 2;
            #pragma unroll
            for (int kk = 0; kk < 4; kk++) {
                uint32_t a[4];
                ldsm4(a, aQ + kk * 32);
                #pragma unroll
                for (int kg = 0; kg < 4; kg++) {
                    uint32_t bb[4];
                    ldsm4(bb, kB + kg * 16 * GPH * 2 + kk * 32);
                    mma16(s[kg * 2], a, bb[0], bb[1]);
                    mma16(s[kg * 2 + 1], a, bb[2], bb[3]);
                }
            }
        }

        // ---- mask + partial row max ----
        float pm0 = -INFINITY, pm1 = -INFINITY;
        #pragma unroll
        for (int ng = 0; ng < 8; ng++) {
            int col = wn * 64 + ng * 8 + tig * 2;
            float mv0 = sMask[col] * (-1e9f), mv1 = sMask[col + 1] * (-1e9f);
            s[ng][0] += mv0; s[ng][1] += mv1;
            s[ng][2] += mv0; s[ng][3] += mv1;
            pm0 = fmaxf(pm0, fmaxf(s[ng][0], s[ng][1]));
            pm1 = fmaxf(pm1, fmaxf(s[ng][2], s[ng][3]));
        }
        pm0 = fmaxf(pm0, __shfl_xor_sync(0xffffffffu, pm0, 1));
        pm0 = fmaxf(pm0, __shfl_xor_sync(0xffffffffu, pm0, 2));
        pm1 = fmaxf(pm1, __shfl_xor_sync(0xffffffffu, pm1, 1));
        pm1 = fmaxf(pm1, __shfl_xor_sync(0xffffffffu, pm1, 2));
        if (tig == 0) { sRM[row0 * 2 + wn] = pm0; sRM[row1 * 2 + wn] = pm1; }
        __syncthreads();

        // prefetch next tile (K reads done; other warps past sync)
        if (t + 1 < 16) { issueK(t + 1); issueV(t + 1); issueM(t + 1); CP_COMMIT(); }

        // ---- combine max, exp, partial sum ----
        float m_new0 = fmaxf(m_run0, fmaxf(pm0, sRM[row0 * 2 + (wn ^ 1)]));
        float m_new1 = fmaxf(m_run1, fmaxf(pm1, sRM[row1 * 2 + (wn ^ 1)]));
        float alpha0 = __expf(m_run0 - m_new0);
        float alpha1 = __expf(m_run1 - m_new1);
        float ps0 = 0.f, ps1 = 0.f;
        #pragma unroll
        for (int ng = 0; ng < 8; ng++) {
            s[ng][0] = __expf(s[ng][0] - m_new0);
            s[ng][1] = __expf(s[ng][1] - m_new0);
            s[ng][2] = __expf(s[ng][2] - m_new1);
            s[ng][3] = __expf(s[ng][3] - m_new1);
            ps0 += s[ng][0] + s[ng][1];
            ps1 += s[ng][2] + s[ng][3];
        }
        ps0 += __shfl_xor_sync(0xffffffffu, ps0, 1);
        ps0 += __shfl_xor_sync(0xffffffffu, ps0, 2);
        ps1 += __shfl_xor_sync(0xffffffffu, ps1, 1);
        ps1 += __shfl_xor_sync(0xffffffffu, ps1, 2);
        if (tig == 0) { sRS[row0 * 2 + wn] = ps0; sRS[row1 * 2 + wn] = ps1; }
        __syncthreads();
        l_run0 = l_run0 * alpha0 + ps0 + sRS[row0 * 2 + (wn ^ 1)];
        l_run1 = l_run1 * alpha1 + ps1 + sRS[row1 * 2 + (wn ^ 1)];
        m_run0 = m_new0; m_run1 = m_new1;

        // ---- P fragments (registers only; C layout == A layout) ----
        uint32_t pf[4][4];
        #pragma unroll
        for (int kc = 0; kc < 4; kc++) {
            pf[kc][0] = h2u(__floats2half2_rn(s[kc * 2][0], s[kc * 2][1]));
            pf[kc][1] = h2u(__floats2half2_rn(s[kc * 2][2], s[kc * 2][3]));
            pf[kc][2] = h2u(__floats2half2_rn(s[kc * 2 + 1][0], s[kc * 2 + 1][1]));
            pf[kc][3] = h2u(__floats2half2_rn(s[kc * 2 + 1][2], s[kc * 2 + 1][3]));
        }

        // ---- O = O*alpha + P @ V ----
        #pragma unroll
        for (int ng = 0; ng < 8; ng++) {
            o[ng][0] *= alpha0; o[ng][1] *= alpha0;
            o[ng][2] *= alpha1; o[ng][3] *= alpha1;
        }
        {
            uint32_t vB = smb + OV + (t & 1) * OVB + (uint32_t)((wn * 64 + rsA) * GPH + csA) * 2;
            #pragma unroll
            for (int kc = 0; kc < 4; kc++) {
                #pragma unroll
                for (int dg = 0; dg < 4; dg++) {
                    uint32_t bb[4];
                    ldsm4t(bb, vB + (uint32_t)(kc * 16 * GPH + dg * 16) * 2);
                    mma16(o[dg * 2], pf[kc], bb[0], bb[1]);
                    mma16(o[dg * 2 + 1], pf[kc], bb[2], bb[3]);
                }
            }
        }
    }

    // ---- epilogue: reduce key-halves across warp pair, normalize, store ----
    float inv0 = 1.f / l_run0, inv1 = 1.f / l_run1;
    float* sO = (float*)sm;   // reuse Q/K area: [128][68] f32
    __syncthreads();
    if (wn == 1) {
        #pragma unroll
        for (int ng = 0; ng < 8; ng++) {
            *(float2*)&sO[row0 * 68 + ng * 8 + tig * 2] = make_float2(o[ng][0], o[ng][1]);
            *(float2*)&sO[row1 * 68 + ng * 8 + tig * 2] = make_float2(o[ng][2], o[ng][3]);
        }
    }
    __syncthreads();
    if (wn == 0) {
        #pragma unroll
        for (int ng = 0; ng < 8; ng++) {
            int col = ng * 8 + tig * 2;
            float2 p0 = *(float2*)&sO[row0 * 68 + col];
            float2 p1 = *(float2*)&sO[row1 * 68 + col];
            __half* C0 = C + ((size_t)(b * Sv + q0 + row0)) * Ev + h * 64 + col;
            __half* C1 = C + ((size_t)(b * Sv + q0 + row1)) * Ev + h * 64 + col;
            *(__half2*)C0 = __floats2half2_rn((o[ng][0] + p0.x) * inv0, (o[ng][1] + p0.y) * inv0);
            *(__half2*)C1 = __floats2half2_rn((o[ng][2] + p1.x) * inv1, (o[ng][3] + p1.y) * inv1);
        }
    }
}

// ---------------------------------------------------------------------------
// LayerNorm(main_out + x)
// ---------------------------------------------------------------------------
__global__ __launch_bounds__(256) void ln_kernel(const float* __restrict__ MO,
                                                 const float* __restrict__ X,
                                                 const float* __restrict__ gamma,
                                                 const float* __restrict__ beta,
                                                 float* __restrict__ out) {
    const int r = blockIdx.x;
    const float* mo = MO + (size_t)r * Ev;
    const float* xr = X + (size_t)r * Ev;

    float v[4];
    float s1 = 0.f, s2 = 0.f;
    #pragma unroll
    for (int i = 0; i < 4; i++) {
        int idx = threadIdx.x + i * 256;
        v[i] = mo[idx] + xr[idx];
        s1 += v[i];
        s2 += v[i] * v[i];
    }
    #pragma unroll
    for (int o = 16; o > 0; o >>= 1) {
        s1 += __shfl_xor_sync(0xffffffffu, s1, o);
        s2 += __shfl_xor_sync(0xffffffffu, s2, o);
    }
    __shared__ float sh1[8], sh2[8], stats[2];
    const int w = threadIdx.x >> 5, lane = threadIdx.x & 31;
    if (lane == 0) { sh1[w] = s1; sh2[w] = s2; }
    __syncthreads();
    if (threadIdx.x == 0) {
        float t1 = 0.f, t2 = 0.f;
        #pragma unroll
        for (int i = 0; i < 8; i++) { t1 += sh1[i]; t2 += sh2[i]; }
        float mu = t1 * (1.f / Ev);
        float var = t2 * (1.f / Ev) - mu * mu;
        stats[0] = mu;
        stats[1] = rsqrtf(var + 1e-6f);
    }
    __syncthreads();
    const float mu = stats[0], rstd = stats[1];
    #pragma unroll
    for (int i = 0; i < 4; i++) {
        int idx = threadIdx.x + i * 256;
        out[(size_t)r * Ev + idx] = gamma[idx] * (v[i] - mu) * rstd + beta[idx];
    }
}

// ---------------------------------------------------------------------------
extern "C" void kernel_launch(void* const* d_in, const int* in_sizes, int n_in,
                              void* d_out, int out_size) {
    const float* x     = (const float*)d_in[0];
    const float* mask  = (const float*)d_in[1];
    const float* Wq    = (const float*)d_in[2];
    const float* bq    = (const float*)d_in[3];
    const float* Wk    = (const float*)d_in[4];
    const float* bk    = (const float*)d_in[5];
    const float* Wv    = (const float*)d_in[6];
    const float* bv    = (const float*)d_in[7];
    const float* Wo    = (const float*)d_in[8];
    const float* bo    = (const float*)d_in[9];
    const float* gamma = (const float*)d_in[10];
    const float* beta  = (const float*)d_in[11];
    float* out = (float*)d_out;

    __half *Xh, *Qh, *Kh, *Vh, *Ch, *WT;
    float *Ob;
    cudaGetSymbolAddress((void**)&Xh, g_Xh);
    cudaGetSymbolAddress((void**)&Qh, g_Qh);
    cudaGetSymbolAddress((void**)&Kh, g_Kh);
    cudaGetSymbolAddress((void**)&Vh, g_Vh);
    cudaGetSymbolAddress((void**)&Ch, g_Ch);
    cudaGetSymbolAddress((void**)&Ob, g_O);
    cudaGetSymbolAddress((void**)&WT, g_WT);
    __half* WTq = WT;
    __half* WTk = WT + 1ull * Ev * Ev;
    __half* WTv = WT + 2ull * Ev * Ev;
    __half* WTo = WT + 3ull * Ev * Ev;

    cudaFuncSetAttribute(gemm_h<true>,  cudaFuncAttributeMaxDynamicSharedMemorySize, GEMM_SMEM);
    cudaFuncSetAttribute(gemm_h<false>, cudaFuncAttributeMaxDynamicSharedMemorySize, GEMM_SMEM);
    cudaFuncSetAttribute(attn_h, cudaFuncAttributeMaxDynamicSharedMemorySize, ATTN_SMEM);

    cvtX<<<BSz * Ev / 1024, 256>>>(x, Xh);
    dim3 tg(32, 32), tb(32, 8);
    cvtW<<<tg, tb>>>(Wq, WTq);
    cvtW<<<tg, tb>>>(Wk, WTk);
    cvtW<<<tg, tb>>>(Wv, WTv);
    cvtW<<<tg, tb>>>(Wo, WTo);

    dim3 gg(8, 64);
    gemm_h<true><<<gg, 512, GEMM_SMEM>>>(Xh, WTq, bq, Qh, 0.03125f);  // fold 1/sqrt(E)
    gemm_h<true><<<gg, 512, GEMM_SMEM>>>(Xh, WTk, bk, Kh, 1.f);
    gemm_h<true><<<gg, 512, GEMM_SMEM>>>(Xh, WTv, bv, Vh, 1.f);

    attn_h<<<dim3(Sv / 128, Bv * Hv), 512, ATTN_SMEM>>>(Qh, Kh, Vh, mask, Ch);

    gemm_h<false><<<gg, 512, GEMM_SMEM>>>(Ch, WTo, bo, Ob, 1.f);

    ln_kernel<<<BSz, 256>>>(Ob, x, gamma, beta, out);
}

// round 11
// speedup vs baseline: 8.9652x; 1.0950x over previous
#include <cuda_runtime.h>
#include <cuda_fp16.h>
#include <cstdint>
#include <math.h>

constexpr int Bv = 4, Sv = 2048, Ev = 1024, Hv = 16;
constexpr int BSz = Bv * Sv;   // 8192

// Scratch (__device__ globals; no allocation)
__device__ __half g_Xh[BSz * Ev];         // fp16 x
__device__ __half g_Qh[BSz * Ev];         // fp16 Q, pre-scaled by 1/32
__device__ __half g_Kh[BSz * Ev];
__device__ __half g_Vh[BSz * Ev];
__device__ __half g_Ch[BSz * Ev];         // fp16 attention context
__device__ float  g_O[BSz * Ev];          // main_out + x (fp32, for LN)
__device__ __half g_WT[4ull * Ev * Ev];   // fp16 transposed weights [n][k]

// ---------------------------------------------------------------------------
// helpers
// ---------------------------------------------------------------------------
__device__ __forceinline__ uint32_t smem_u32(const void* p) {
    uint32_t a;
    asm("{ .reg .u64 t; cvta.to.shared.u64 t, %1; cvt.u32.u64 %0, t; }" : "=r"(a) : "l"(p));
    return a;
}
__device__ __forceinline__ void mma16(float* d, const uint32_t* a, uint32_t b0, uint32_t b1) {
    asm volatile(
        "mma.sync.aligned.m16n8k16.row.col.f32.f16.f16.f32 "
        "{%0,%1,%2,%3}, {%4,%5,%6,%7}, {%8,%9}, {%0,%1,%2,%3};"
        : "+f"(d[0]), "+f"(d[1]), "+f"(d[2]), "+f"(d[3])
        : "r"(a[0]), "r"(a[1]), "r"(a[2]), "r"(a[3]), "r"(b0), "r"(b1));
}
__device__ __forceinline__ void ldsm4(uint32_t* r, uint32_t addr) {
    asm volatile("ldmatrix.sync.aligned.m8n8.x4.shared.b16 {%0,%1,%2,%3}, [%4];"
                 : "=r"(r[0]), "=r"(r[1]), "=r"(r[2]), "=r"(r[3]) : "r"(addr));
}
__device__ __forceinline__ void ldsm4t(uint32_t* r, uint32_t addr) {
    asm volatile("ldmatrix.sync.aligned.m8n8.x4.trans.shared.b16 {%0,%1,%2,%3}, [%4];"
                 : "=r"(r[0]), "=r"(r[1]), "=r"(r[2]), "=r"(r[3]) : "r"(addr));
}
__device__ __forceinline__ void cpa16(uint32_t dst, const void* src) {
    asm volatile("cp.async.cg.shared.global [%0], [%1], 16;" :: "r"(dst), "l"(src));
}
#define CP_COMMIT() asm volatile("cp.async.commit_group;" ::: "memory")
#define CP_WAIT(n)  asm volatile("cp.async.wait_group %0;" :: "n"(n) : "memory")
__device__ __forceinline__ uint32_t h2u(__half2 h) { return *(uint32_t*)&h; }

// ---------------------------------------------------------------------------
// prep: fp32 -> fp16 convert / fused transpose-convert of 4 weight matrices
// ---------------------------------------------------------------------------
__global__ void cvtX(const float* __restrict__ in, __half* __restrict__ out) {
    size_t i = ((size_t)blockIdx.x * 256 + threadIdx.x) * 4;
    float4 v = *(const float4*)(in + i);
    __half2* o = (__half2*)(out + i);
    o[0] = __floats2half2_rn(v.x, v.y);
    o[1] = __floats2half2_rn(v.z, v.w);
}
__global__ void cvtW4(const float* __restrict__ W0, const float* __restrict__ W1,
                      const float* __restrict__ W2, const float* __restrict__ W3,
                      __half* __restrict__ out) {
    __shared__ float t[32][33];
    const float* in = (blockIdx.z == 0) ? W0 : (blockIdx.z == 1) ? W1
                    : (blockIdx.z == 2) ? W2 : W3;
    __half* op = out + (size_t)blockIdx.z * Ev * Ev;
    int k0 = blockIdx.y * 32, n0 = blockIdx.x * 32;
    for (int i = threadIdx.y; i < 32; i += 8)
        t[i][threadIdx.x] = in[(size_t)(k0 + i) * 1024 + n0 + threadIdx.x];
    __syncthreads();
    for (int i = threadIdx.y; i < 32; i += 8)
        op[(size_t)(n0 + i) * 1024 + k0 + threadIdx.x] = __float2half(t[threadIdx.x][i]);
}

// ---------------------------------------------------------------------------
// fp16 GEMM: C = A @ WT^T + bias (*scale); HOUT=false adds fp32 residual X.
// 512 thr, warp grid 4x4, CTA tile 128x128, K-chunk 64, 3-stage cp.async.
// ---------------------------------------------------------------------------
constexpr int GPH = 72;
constexpr int GSTB = 2 * 128 * GPH * 2;   // stage bytes = 36864
constexpr int GEMM_SMEM = 3 * GSTB;       // 110592

template <bool HOUT>
__global__ __launch_bounds__(512) void gemm_h(const __half* __restrict__ A,
                                              const __half* __restrict__ WT,
                                              const float* __restrict__ bias,
                                              void* __restrict__ Cout, float scale,
                                              const float* __restrict__ Xres) {
    extern __shared__ char sm[];
    const int tid = threadIdx.x, wid = tid >> 5, lane = tid & 31;
    const int gid = lane >> 2, tig = lane & 3;
    const int wm = wid >> 2, wn = wid & 3;
    const int m0 = blockIdx.y * 128, n0 = blockIdx.x * 128;
    const uint32_t smb = smem_u32(sm);
    const int rsA = lane & 15, csA = (lane >> 4) * 8;
    const int rsB = (lane & 7) + ((lane >> 4) & 1) * 8, csB = ((lane >> 3) & 1) * 8;

    auto issue = [&](int c) {
        uint32_t dA = smb + (uint32_t)((c % 3) * GSTB);
        uint32_t dB = dA + 128 * GPH * 2;
        const __half* pa = A  + (size_t)m0 * 1024 + c * 64;
        const __half* pb = WT + (size_t)n0 * 1024 + c * 64;
        #pragma unroll
        for (int i = 0; i < 2; i++) {
            int unit = tid + i * 512, r = unit >> 3, u = unit & 7;
            cpa16(dA + (uint32_t)(r * GPH + u * 8) * 2, pa + (size_t)r * 1024 + u * 8);
            cpa16(dB + (uint32_t)(r * GPH + u * 8) * 2, pb + (size_t)r * 1024 + u * 8);
        }
    };

    float acc[2][4][4] = {};
    issue(0); CP_COMMIT();
    issue(1); CP_COMMIT();

    for (int c = 0; c < 16; c++) {
        CP_WAIT(1);
        __syncthreads();
        if (c + 2 < 16) issue(c + 2);
        CP_COMMIT();   // always commit (possibly empty) so CP_WAIT(1) pins group c+1
        uint32_t bA = smb + (uint32_t)((c % 3) * GSTB);
        uint32_t aB0 = bA + (uint32_t)((wm * 32 + rsA) * GPH + csA) * 2;
        uint32_t aB1 = aB0 + 16 * GPH * 2;
        uint32_t bB0 = bA + 128 * GPH * 2 + (uint32_t)((wn * 32 + rsB) * GPH + csB) * 2;
        uint32_t bB1 = bB0 + 16 * GPH * 2;
        #pragma unroll
        for (int kk = 0; kk < 4; kk++) {
            uint32_t a[2][4], bb[2][4];
            ldsm4(a[0], aB0 + kk * 32);
            ldsm4(a[1], aB1 + kk * 32);
            ldsm4(bb[0], bB0 + kk * 32);
            ldsm4(bb[1], bB1 + kk * 32);
            #pragma unroll
            for (int mt = 0; mt < 2; mt++)
                #pragma unroll
                for (int nt = 0; nt < 4; nt++)
                    mma16(acc[mt][nt], a[mt], bb[nt >> 1][(nt & 1) * 2],
                          bb[nt >> 1][(nt & 1) * 2 + 1]);
        }
        // no bottom sync: next iteration's top sync orders stage reuse (3 stages)
    }

    #pragma unroll
    for (int mt = 0; mt < 2; mt++) {
        int row = m0 + wm * 32 + mt * 16 + gid;
        #pragma unroll
        for (int nt = 0; nt < 4; nt++) {
            int col = n0 + wn * 32 + nt * 8 + tig * 2;
            float b0 = bias[col], b1 = bias[col + 1];
            float v0 = (acc[mt][nt][0] + b0) * scale, v1 = (acc[mt][nt][1] + b1) * scale;
            float v2 = (acc[mt][nt][2] + b0) * scale, v3 = (acc[mt][nt][3] + b1) * scale;
            if (HOUT) {
                __half* C = (__half*)Cout;
                *(__half2*)(C + (size_t)row * 1024 + col) = __floats2half2_rn(v0, v1);
                *(__half2*)(C + (size_t)(row + 8) * 1024 + col) = __floats2half2_rn(v2, v3);
            } else {
                float* C = (float*)Cout;
                float2 x0 = *(const float2*)(Xres + (size_t)row * 1024 + col);
                float2 x1 = *(const float2*)(Xres + (size_t)(row + 8) * 1024 + col);
                *(float2*)(C + (size_t)row * 1024 + col) = make_float2(v0 + x0.x, v1 + x0.y);
                *(float2*)(C + (size_t)(row + 8) * 1024 + col) = make_float2(v2 + x1.x, v3 + x1.y);
            }
        }
    }
}

// ---------------------------------------------------------------------------
// fp16 flash attention, split-softmax across key-halves.
// 512 thr = 16 warps as 8(q) x 2(key-half).  CTA: 128 q; 16 key tiles of 128.
// Each half keeps independent (m, l, O); merged once at the end.
// 2 syncthreads per tile; softmax is pure register/shfl work.
// ---------------------------------------------------------------------------
constexpr int OQ = 0, OK = 18432, OV = 36864, OVB = 18432;
constexpr int OM = 73728, ORM = 74240, ORS = 75264;
constexpr int ATTN_SMEM = 76288;

__global__ __launch_bounds__(512) void attn_h(const __half* __restrict__ Q,
                                              const __half* __restrict__ Kg,
                                              const __half* __restrict__ Vg,
                                              const float* __restrict__ mask,
                                              __half* __restrict__ C) {
    extern __shared__ char sm[];
    const int tid = threadIdx.x, wid = tid >> 5, lane = tid & 31;
    const int gid = lane >> 2, tig = lane & 3;
    const int wm = wid >> 1, wn = wid & 1;       // 8 x 2 warp grid
    const int b = blockIdx.y >> 4, h = blockIdx.y & 15;
    const int q0 = blockIdx.x * 128;
    const uint32_t smb = smem_u32(sm);
    const int rsA = lane & 15, csA = (lane >> 4) * 8;
    const int rsB = (lane & 7) + ((lane >> 4) & 1) * 8;
    const int csB = ((lane >> 3) & 1) * 8;

    const __half* Qg  = Q  + ((size_t)(b * Sv + q0)) * Ev + h * 64;
    const __half* Kgp = Kg + ((size_t)b * Sv) * Ev + h * 64;
    const __half* Vgp = Vg + ((size_t)b * Sv) * Ev + h * 64;

    auto issueK = [&](int t) {
        const __half* p = Kgp + (size_t)(t * 128) * Ev;
        #pragma unroll
        for (int i = 0; i < 2; i++) {
            int unit = tid + i * 512, r = unit >> 3, u = unit & 7;
            cpa16(smb + OK + (uint32_t)(r * GPH + u * 8) * 2, p + (size_t)r * Ev + u * 8);
        }
    };
    auto issueV = [&](int t) {
        const __half* p = Vgp + (size_t)(t * 128) * Ev;
        uint32_t dst = smb + OV + (t & 1) * OVB;
        #pragma unroll
        for (int i = 0; i < 2; i++) {
            int unit = tid + i * 512, r = unit >> 3, u = unit & 7;
            cpa16(dst + (uint32_t)(r * GPH + u * 8) * 2, p + (size_t)r * Ev + u * 8);
        }
    };
    auto issueM = [&](int t) {
        if (tid < 32)
            cpa16(smb + OM + tid * 16, mask + (size_t)b * Sv + t * 128 + tid * 4);
    };

    #pragma unroll
    for (int i = 0; i < 2; i++) {
        int unit = tid + i * 512, r = unit >> 3, u = unit & 7;
        cpa16(smb + OQ + (uint32_t)(r * GPH + u * 8) * 2, Qg + (size_t)r * Ev + u * 8);
    }
    issueK(0); issueV(0); issueM(0);
    CP_COMMIT();

    float o[8][4] = {};
    float m_run0 = -INFINITY, m_run1 = -INFINITY, l_run0 = 0.f, l_run1 = 0.f;
    float* sMask = (float*)(sm + OM);
    const int row0 = wm * 16 + gid, row1 = row0 + 8;

    for (int t = 0; t < 16; t++) {
        CP_WAIT(0);
        __syncthreads();

        // ---- S = Q @ K^T : warp computes 16q x 64keys (its half) ----
        float s[8][4] = {};
        {
            uint32_t aQ = smb + OQ + (uint32_t)((wm * 16 + rsA) * GPH + csA) * 2;
            uint32_t kB = smb + OK + (uint32_t)((wn * 64 + rsB) * GPH + csB) * 2;
            #pragma unroll
            for (int kk = 0; kk < 4; kk++) {
                uint32_t a[4];
                ldsm4(a, aQ + kk * 32);
                #pragma unroll
                for (int kg = 0; kg < 4; kg++) {
                    uint32_t bb[4];
                    ldsm4(bb, kB + kg * 16 * GPH * 2 + kk * 32);
                    mma16(s[kg * 2], a, bb[0], bb[1]);
                    mma16(s[kg * 2 + 1], a, bb[2], bb[3]);
                }
            }
        }

        // ---- mask + local row max (before sync: sMask still tile t) ----
        float pm0 = -INFINITY, pm1 = -INFINITY;
        #pragma unroll
        for (int ng = 0; ng < 8; ng++) {
            int col = wn * 64 + ng * 8 + tig * 2;
            float mv0 = sMask[col] * (-1e9f), mv1 = sMask[col + 1] * (-1e9f);
            s[ng][0] += mv0; s[ng][1] += mv1;
            s[ng][2] += mv0; s[ng][3] += mv1;
            pm0 = fmaxf(pm0, fmaxf(s[ng][0], s[ng][1]));
            pm1 = fmaxf(pm1, fmaxf(s[ng][2], s[ng][3]));
        }
        __syncthreads();   // K + mask reads of tile t complete everywhere
        if (t + 1 < 16) { issueK(t + 1); issueV(t + 1); issueM(t + 1); CP_COMMIT(); }

        // ---- independent online softmax for this half (regs + shfl only) ----
        pm0 = fmaxf(pm0, __shfl_xor_sync(0xffffffffu, pm0, 1));
        pm0 = fmaxf(pm0, __shfl_xor_sync(0xffffffffu, pm0, 2));
        pm1 = fmaxf(pm1, __shfl_xor_sync(0xffffffffu, pm1, 1));
        pm1 = fmaxf(pm1, __shfl_xor_sync(0xffffffffu, pm1, 2));
        float m_new0 = fmaxf(m_run0, pm0);
        float m_new1 = fmaxf(m_run1, pm1);
        float alpha0 = __expf(m_run0 - m_new0);
        float alpha1 = __expf(m_run1 - m_new1);
        float ps0 = 0.f, ps1 = 0.f;
        #pragma unroll
        for (int ng = 0; ng < 8; ng++) {
            s[ng][0] = __expf(s[ng][0] - m_new0);
            s[ng][1] = __expf(s[ng][1] - m_new0);
            s[ng][2] = __expf(s[ng][2] - m_new1);
            s[ng][3] = __expf(s[ng][3] - m_new1);
            ps0 += s[ng][0] + s[ng][1];
            ps1 += s[ng][2] + s[ng][3];
        }
        ps0 += __shfl_xor_sync(0xffffffffu, ps0, 1);
        ps0 += __shfl_xor_sync(0xffffffffu, ps0, 2);
        ps1 += __shfl_xor_sync(0xffffffffu, ps1, 1);
        ps1 += __shfl_xor_sync(0xffffffffu, ps1, 2);
        l_run0 = l_run0 * alpha0 + ps0;
        l_run1 = l_run1 * alpha1 + ps1;
        m_run0 = m_new0; m_run1 = m_new1;

        uint32_t pf[4][4];
        #pragma unroll
        for (int kc = 0; kc < 4; kc++) {
            pf[kc][0] = h2u(__floats2half2_rn(s[kc * 2][0], s[kc * 2][1]));
            pf[kc][1] = h2u(__floats2half2_rn(s[kc * 2][2], s[kc * 2][3]));
            pf[kc][2] = h2u(__floats2half2_rn(s[kc * 2 + 1][0], s[kc * 2 + 1][1]));
            pf[kc][3] = h2u(__floats2half2_rn(s[kc * 2 + 1][2], s[kc * 2 + 1][3]));
        }

        #pragma unroll
        for (int ng = 0; ng < 8; ng++) {
            o[ng][0] *= alpha0; o[ng][1] *= alpha0;
            o[ng][2] *= alpha1; o[ng][3] *= alpha1;
        }
        {
            uint32_t vB = smb + OV + (t & 1) * OVB + (uint32_t)((wn * 64 + rsA) * GPH + csA) * 2;
            #pragma unroll
            for (int kc = 0; kc < 4; kc++) {
                #pragma unroll
                for (int dg = 0; dg < 4; dg++) {
                    uint32_t bb[4];
                    ldsm4t(bb, vB + (uint32_t)(kc * 16 * GPH + dg * 16) * 2);
                    mma16(o[dg * 2], pf[kc], bb[0], bb[1]);
                    mma16(o[dg * 2 + 1], pf[kc], bb[2], bb[3]);
                }
            }
        }
    }

    // ---- merge the two key-half softmax states, normalize, store ----
    float* sM = (float*)(sm + ORM);   // [128][2] per-half row max
    float* sL = (float*)(sm + ORS);   // [128][2] per-half row sum
    if (tig == 0) {
        sM[row0 * 2 + wn] = m_run0;  sM[row1 * 2 + wn] = m_run1;
        sL[row0 * 2 + wn] = l_run0;  sL[row1 * 2 + wn] = l_run1;
    }
    __syncthreads();
    float mo0 = sM[row0 * 2 + (wn ^ 1)], mo1 = sM[row1 * 2 + (wn ^ 1)];
    float lo0 = sL[row0 * 2 + (wn ^ 1)], lo1 = sL[row1 * 2 + (wn ^ 1)];
    float mg0 = fmaxf(m_run0, mo0), mg1 = fmaxf(m_run1, mo1);
    float be0 = __expf(m_run0 - mg0), be1 = __expf(m_run1 - mg1);
    float beo0 = __expf(mo0 - mg0),  beo1 = __expf(mo1 - mg1);
    float lg0 = l_run0 * be0 + lo0 * beo0;
    float lg1 = l_run1 * be1 + lo1 * beo1;

    float* sO = (float*)sm;   // reuse Q/K area: [128][68] f32 (dead after last sync)
    if (wn == 1) {
        #pragma unroll
        for (int ng = 0; ng < 8; ng++) {
            *(float2*)&sO[row0 * 68 + ng * 8 + tig * 2] =
                make_float2(o[ng][0] * be0, o[ng][1] * be0);
            *(float2*)&sO[row1 * 68 + ng * 8 + tig * 2] =
                make_float2(o[ng][2] * be1, o[ng][3] * be1);
        }
    }
    __syncthreads();
    if (wn == 0) {
        float inv0 = 1.f / lg0, inv1 = 1.f / lg1;
        #pragma unroll
        for (int ng = 0; ng < 8; ng++) {
            int col = ng * 8 + tig * 2;
            float2 p0 = *(float2*)&sO[row0 * 68 + col];
            float2 p1 = *(float2*)&sO[row1 * 68 + col];
            __half* C0 = C + ((size_t)(b * Sv + q0 + row0)) * Ev + h * 64 + col;
            __half* C1 = C + ((size_t)(b * Sv + q0 + row1)) * Ev + h * 64 + col;
            *(__half2*)C0 = __floats2half2_rn((o[ng][0] * be0 + p0.x) * inv0,
                                              (o[ng][1] * be0 + p0.y) * inv0);
            *(__half2*)C1 = __floats2half2_rn((o[ng][2] * be1 + p1.x) * inv1,
                                              (o[ng][3] * be1 + p1.y) * inv1);
        }
    }
}

// ---------------------------------------------------------------------------
// LayerNorm(pre-added main_out + x)
// ---------------------------------------------------------------------------
__global__ __launch_bounds__(256) void ln_kernel(const float* __restrict__ MO,
                                                 const float* __restrict__ gamma,
                                                 const float* __restrict__ beta,
                                                 float* __restrict__ out) {
    const int r = blockIdx.x;
    const float* mo = MO + (size_t)r * Ev;

    float v[4];
    float s1 = 0.f, s2 = 0.f;
    #pragma unroll
    for (int i = 0; i < 4; i++) {
        int idx = threadIdx.x + i * 256;
        v[i] = mo[idx];
        s1 += v[i];
        s2 += v[i] * v[i];
    }
    #pragma unroll
    for (int o = 16; o > 0; o >>= 1) {
        s1 += __shfl_xor_sync(0xffffffffu, s1, o);
        s2 += __shfl_xor_sync(0xffffffffu, s2, o);
    }
    __shared__ float sh1[8], sh2[8], stats[2];
    const int w = threadIdx.x >> 5, lane = threadIdx.x & 31;
    if (lane == 0) { sh1[w] = s1; sh2[w] = s2; }
    __syncthreads();
    if (threadIdx.x == 0) {
        float t1 = 0.f, t2 = 0.f;
        #pragma unroll
        for (int i = 0; i < 8; i++) { t1 += sh1[i]; t2 += sh2[i]; }
        float mu = t1 * (1.f / Ev);
        float var = t2 * (1.f / Ev) - mu * mu;
        stats[0] = mu;
        stats[1] = rsqrtf(var + 1e-6f);
    }
    __syncthreads();
    const float mu = stats[0], rstd = stats[1];
    #pragma unroll
    for (int i = 0; i < 4; i++) {
        int idx = threadIdx.x + i * 256;
        out[(size_t)r * Ev + idx] = gamma[idx] * (v[i] - mu) * rstd + beta[idx];
    }
}

// ---------------------------------------------------------------------------
extern "C" void kernel_launch(void* const* d_in, const int* in_sizes, int n_in,
                              void* d_out, int out_size) {
    const float* x     = (const float*)d_in[0];
    const float* mask  = (const float*)d_in[1];
    const float* Wq    = (const float*)d_in[2];
    const float* bq    = (const float*)d_in[3];
    const float* Wk    = (const float*)d_in[4];
    const float* bk    = (const float*)d_in[5];
    const float* Wv    = (const float*)d_in[6];
    const float* bv    = (const float*)d_in[7];
    const float* Wo    = (const float*)d_in[8];
    const float* bo    = (const float*)d_in[9];
    const float* gamma = (const float*)d_in[10];
    const float* beta  = (const float*)d_in[11];
    float* out = (float*)d_out;

    __half *Xh, *Qh, *Kh, *Vh, *Ch, *WT;
    float *Ob;
    cudaGetSymbolAddress((void**)&Xh, g_Xh);
    cudaGetSymbolAddress((void**)&Qh, g_Qh);
    cudaGetSymbolAddress((void**)&Kh, g_Kh);
    cudaGetSymbolAddress((void**)&Vh, g_Vh);
    cudaGetSymbolAddress((void**)&Ch, g_Ch);
    cudaGetSymbolAddress((void**)&Ob, g_O);
    cudaGetSymbolAddress((void**)&WT, g_WT);
    __half* WTq = WT;
    __half* WTk = WT + 1ull * Ev * Ev;
    __half* WTv = WT + 2ull * Ev * Ev;
    __half* WTo = WT + 3ull * Ev * Ev;

    cudaFuncSetAttribute(gemm_h<true>,  cudaFuncAttributeMaxDynamicSharedMemorySize, GEMM_SMEM);
    cudaFuncSetAttribute(gemm_h<false>, cudaFuncAttributeMaxDynamicSharedMemorySize, GEMM_SMEM);
    cudaFuncSetAttribute(attn_h, cudaFuncAttributeMaxDynamicSharedMemorySize, ATTN_SMEM);

    cvtX<<<BSz * Ev / 1024, 256>>>(x, Xh);
    cvtW4<<<dim3(32, 32, 4), dim3(32, 8)>>>(Wq, Wk, Wv, Wo, WT);

    dim3 gg(8, 64);
    gemm_h<true><<<gg, 512, GEMM_SMEM>>>(Xh, WTq, bq, Qh, 0.03125f, nullptr);
    gemm_h<true><<<gg, 512, GEMM_SMEM>>>(Xh, WTk, bk, Kh, 1.f, nullptr);
    gemm_h<true><<<gg, 512, GEMM_SMEM>>>(Xh, WTv, bv, Vh, 1.f, nullptr);

    attn_h<<<dim3(Sv / 128, Bv * Hv), 512, ATTN_SMEM>>>(Qh, Kh, Vh, mask, Ch);

    gemm_h<false><<<gg, 512, GEMM_SMEM>>>(Ch, WTo, bo, Ob, 1.f, x);

    ln_kernel<<<BSz, 256>>>(Ob, gamma, beta, out);
}

// round 12
// speedup vs baseline: 8.9974x; 1.0036x over previous
#include <cuda_runtime.h>
#include <cuda_fp16.h>
#include <cstdint>
#include <math.h>

constexpr int Bv = 4, Sv = 2048, Ev = 1024, Hv = 16;
constexpr int BSz = Bv * Sv;   // 8192

// Scratch (__device__ globals; no allocation)
__device__ __half g_Xh[BSz * Ev];         // fp16 x
__device__ __half g_Qh[BSz * Ev];         // fp16 Q, pre-scaled by 1/32
__device__ __half g_Kh[BSz * Ev];
__device__ __half g_Vh[BSz * Ev];
__device__ __half g_Ch[BSz * Ev];         // fp16 attention context
__device__ float  g_O[BSz * Ev];          // main_out + x (fp32, for LN)
__device__ __half g_WT[4ull * Ev * Ev];   // fp16 transposed weights [n][k]

// ---------------------------------------------------------------------------
// helpers
// ---------------------------------------------------------------------------
__device__ __forceinline__ uint32_t smem_u32(const void* p) {
    uint32_t a;
    asm("{ .reg .u64 t; cvta.to.shared.u64 t, %1; cvt.u32.u64 %0, t; }" : "=r"(a) : "l"(p));
    return a;
}
__device__ __forceinline__ void mma16(float* d, const uint32_t* a, uint32_t b0, uint32_t b1) {
    asm volatile(
        "mma.sync.aligned.m16n8k16.row.col.f32.f16.f16.f32 "
        "{%0,%1,%2,%3}, {%4,%5,%6,%7}, {%8,%9}, {%0,%1,%2,%3};"
        : "+f"(d[0]), "+f"(d[1]), "+f"(d[2]), "+f"(d[3])
        : "r"(a[0]), "r"(a[1]), "r"(a[2]), "r"(a[3]), "r"(b0), "r"(b1));
}
__device__ __forceinline__ void ldsm4(uint32_t* r, uint32_t addr) {
    asm volatile("ldmatrix.sync.aligned.m8n8.x4.shared.b16 {%0,%1,%2,%3}, [%4];"
                 : "=r"(r[0]), "=r"(r[1]), "=r"(r[2]), "=r"(r[3]) : "r"(addr));
}
__device__ __forceinline__ void ldsm4t(uint32_t* r, uint32_t addr) {
    asm volatile("ldmatrix.sync.aligned.m8n8.x4.trans.shared.b16 {%0,%1,%2,%3}, [%4];"
                 : "=r"(r[0]), "=r"(r[1]), "=r"(r[2]), "=r"(r[3]) : "r"(addr));
}
__device__ __forceinline__ void cpa16(uint32_t dst, const void* src) {
    asm volatile("cp.async.cg.shared.global [%0], [%1], 16;" :: "r"(dst), "l"(src));
}
#define CP_COMMIT() asm volatile("cp.async.commit_group;" ::: "memory")
#define CP_WAIT(n)  asm volatile("cp.async.wait_group %0;" :: "n"(n) : "memory")
__device__ __forceinline__ uint32_t h2u(__half2 h) { return *(uint32_t*)&h; }

// ---------------------------------------------------------------------------
// prep: fp32 -> fp16 convert / fused transpose-convert of 4 weight matrices
// ---------------------------------------------------------------------------
__global__ void cvtX(const float* __restrict__ in, __half* __restrict__ out) {
    size_t i = ((size_t)blockIdx.x * 256 + threadIdx.x) * 4;
    float4 v = *(const float4*)(in + i);
    __half2* o = (__half2*)(out + i);
    o[0] = __floats2half2_rn(v.x, v.y);
    o[1] = __floats2half2_rn(v.z, v.w);
}
__global__ void cvtW4(const float* __restrict__ W0, const float* __restrict__ W1,
                      const float* __restrict__ W2, const float* __restrict__ W3,
                      __half* __restrict__ out) {
    __shared__ float t[32][33];
    const float* in = (blockIdx.z == 0) ? W0 : (blockIdx.z == 1) ? W1
                    : (blockIdx.z == 2) ? W2 : W3;
    __half* op = out + (size_t)blockIdx.z * Ev * Ev;
    int k0 = blockIdx.y * 32, n0 = blockIdx.x * 32;
    for (int i = threadIdx.y; i < 32; i += 8)
        t[i][threadIdx.x] = in[(size_t)(k0 + i) * 1024 + n0 + threadIdx.x];
    __syncthreads();
    for (int i = threadIdx.y; i < 32; i += 8)
        op[(size_t)(n0 + i) * 1024 + k0 + threadIdx.x] = __float2half(t[threadIdx.x][i]);
}

// ---------------------------------------------------------------------------
// fp16 GEMM: C = A @ WT^T + bias (*scale); HOUT=false adds fp32 residual X.
// 256 thr, 8 warps (2M x 4N), warp tile 64x32, CTA tile 128x128,
// K-chunk 64, 3-stage cp.async.  Per k16: 6 ldmatrix.x4 -> 16 MMAs (ratio 2.67).
// ---------------------------------------------------------------------------
constexpr int GPH = 72;
constexpr int GSTB = 2 * 128 * GPH * 2;   // stage bytes = 36864
constexpr int GEMM_SMEM = 3 * GSTB;       // 110592

template <bool HOUT>
__global__ __launch_bounds__(256) void gemm_h(const __half* __restrict__ A,
                                              const __half* __restrict__ WT,
                                              const float* __restrict__ bias,
                                              void* __restrict__ Cout, float scale,
                                              const float* __restrict__ Xres) {
    extern __shared__ char sm[];
    const int tid = threadIdx.x, wid = tid >> 5, lane = tid & 31;
    const int gid = lane >> 2, tig = lane & 3;
    const int wm = wid >> 2, wn = wid & 3;        // 2 x 4 warp grid
    const int m0 = blockIdx.y * 128, n0 = blockIdx.x * 128;
    const uint32_t smb = smem_u32(sm);
    const int rsA = lane & 15, csA = (lane >> 4) * 8;
    const int rsB = (lane & 7) + ((lane >> 4) & 1) * 8, csB = ((lane >> 3) & 1) * 8;

    auto issue = [&](int c) {
        uint32_t dA = smb + (uint32_t)((c % 3) * GSTB);
        uint32_t dB = dA + 128 * GPH * 2;
        const __half* pa = A  + (size_t)m0 * 1024 + c * 64;
        const __half* pb = WT + (size_t)n0 * 1024 + c * 64;
        #pragma unroll
        for (int i = 0; i < 4; i++) {
            int unit = tid + i * 256, r = unit >> 3, u = unit & 7;
            cpa16(dA + (uint32_t)(r * GPH + u * 8) * 2, pa + (size_t)r * 1024 + u * 8);
            cpa16(dB + (uint32_t)(r * GPH + u * 8) * 2, pb + (size_t)r * 1024 + u * 8);
        }
    };

    float acc[4][4][4] = {};
    issue(0); CP_COMMIT();
    issue(1); CP_COMMIT();

    for (int c = 0; c < 16; c++) {
        CP_WAIT(1);
        __syncthreads();
        if (c + 2 < 16) issue(c + 2);
        CP_COMMIT();   // always commit (possibly empty) so CP_WAIT(1) pins group c+1
        uint32_t bA = smb + (uint32_t)((c % 3) * GSTB);
        uint32_t aB0 = bA + (uint32_t)((wm * 64 + rsA) * GPH + csA) * 2;
        uint32_t bB0 = bA + 128 * GPH * 2 + (uint32_t)((wn * 32 + rsB) * GPH + csB) * 2;
        uint32_t bB1 = bB0 + 16 * GPH * 2;
        #pragma unroll
        for (int kk = 0; kk < 4; kk++) {
            uint32_t a[4][4], bb[2][4];
            #pragma unroll
            for (int mt = 0; mt < 4; mt++)
                ldsm4(a[mt], aB0 + (uint32_t)(mt * 16 * GPH) * 2 + kk * 32);
            ldsm4(bb[0], bB0 + kk * 32);
            ldsm4(bb[1], bB1 + kk * 32);
            #pragma unroll
            for (int mt = 0; mt < 4; mt++)
                #pragma unroll
                for (int nt = 0; nt < 4; nt++)
                    mma16(acc[mt][nt], a[mt], bb[nt >> 1][(nt & 1) * 2],
                          bb[nt >> 1][(nt & 1) * 2 + 1]);
        }
        // no bottom sync: next iteration's top sync orders stage reuse (3 stages)
    }

    #pragma unroll
    for (int mt = 0; mt < 4; mt++) {
        int row = m0 + wm * 64 + mt * 16 + gid;
        #pragma unroll
        for (int nt = 0; nt < 4; nt++) {
            int col = n0 + wn * 32 + nt * 8 + tig * 2;
            float b0 = bias[col], b1 = bias[col + 1];
            float v0 = (acc[mt][nt][0] + b0) * scale, v1 = (acc[mt][nt][1] + b1) * scale;
            float v2 = (acc[mt][nt][2] + b0) * scale, v3 = (acc[mt][nt][3] + b1) * scale;
            if (HOUT) {
                __half* C = (__half*)Cout;
                *(__half2*)(C + (size_t)row * 1024 + col) = __floats2half2_rn(v0, v1);
                *(__half2*)(C + (size_t)(row + 8) * 1024 + col) = __floats2half2_rn(v2, v3);
            } else {
                float* C = (float*)Cout;
                float2 x0 = *(const float2*)(Xres + (size_t)row * 1024 + col);
                float2 x1 = *(const float2*)(Xres + (size_t)(row + 8) * 1024 + col);
                *(float2*)(C + (size_t)row * 1024 + col) = make_float2(v0 + x0.x, v1 + x0.y);
                *(float2*)(C + (size_t)(row + 8) * 1024 + col) = make_float2(v2 + x1.x, v3 + x1.y);
            }
        }
    }
}

// ---------------------------------------------------------------------------
// fp16 flash attention, split-softmax across key-halves (unchanged from R11).
// ---------------------------------------------------------------------------
constexpr int OQ = 0, OK = 18432, OV = 36864, OVB = 18432;
constexpr int OM = 73728, ORM = 74240, ORS = 75264;
constexpr int ATTN_SMEM = 76288;

__global__ __launch_bounds__(512) void attn_h(const __half* __restrict__ Q,
                                              const __half* __restrict__ Kg,
                                              const __half* __restrict__ Vg,
                                              const float* __restrict__ mask,
                                              __half* __restrict__ C) {
    extern __shared__ char sm[];
    const int tid = threadIdx.x, wid = tid >> 5, lane = tid & 31;
    const int gid = lane >> 2, tig = lane & 3;
    const int wm = wid >> 1, wn = wid & 1;       // 8 x 2 warp grid
    const int b = blockIdx.y >> 4, h = blockIdx.y & 15;
    const int q0 = blockIdx.x * 128;
    const uint32_t smb = smem_u32(sm);
    const int rsA = lane & 15, csA = (lane >> 4) * 8;
    const int rsB = (lane & 7) + ((lane >> 4) & 1) * 8;
    const int csB = ((lane >> 3) & 1) * 8;

    const __half* Qg  = Q  + ((size_t)(b * Sv + q0)) * Ev + h * 64;
    const __half* Kgp = Kg + ((size_t)b * Sv) * Ev + h * 64;
    const __half* Vgp = Vg + ((size_t)b * Sv) * Ev + h * 64;

    auto issueK = [&](int t) {
        const __half* p = Kgp + (size_t)(t * 128) * Ev;
        #pragma unroll
        for (int i = 0; i < 2; i++) {
            int unit = tid + i * 512, r = unit >> 3, u = unit & 7;
            cpa16(smb + OK + (uint32_t)(r * GPH + u * 8) * 2, p + (size_t)r * Ev + u * 8);
        }
    };
    auto issueV = [&](int t) {
        const __half* p = Vgp + (size_t)(t * 128) * Ev;
        uint32_t dst = smb + OV + (t & 1) * OVB;
        #pragma unroll
        for (int i = 0; i < 2; i++) {
            int unit = tid + i * 512, r = unit >> 3, u = unit & 7;
            cpa16(dst + (uint32_t)(r * GPH + u * 8) * 2, p + (size_t)r * Ev + u * 8);
        }
    };
    auto issueM = [&](int t) {
        if (tid < 32)
            cpa16(smb + OM + tid * 16, mask + (size_t)b * Sv + t * 128 + tid * 4);
    };

    #pragma unroll
    for (int i = 0; i < 2; i++) {
        int unit = tid + i * 512, r = unit >> 3, u = unit & 7;
        cpa16(smb + OQ + (uint32_t)(r * GPH + u * 8) * 2, Qg + (size_t)r * Ev + u * 8);
    }
    issueK(0); issueV(0); issueM(0);
    CP_COMMIT();

    float o[8][4] = {};
    float m_run0 = -INFINITY, m_run1 = -INFINITY, l_run0 = 0.f, l_run1 = 0.f;
    float* sMask = (float*)(sm + OM);
    const int row0 = wm * 16 + gid, row1 = row0 + 8;

    for (int t = 0; t < 16; t++) {
        CP_WAIT(0);
        __syncthreads();

        float s[8][4] = {};
        {
            uint32_t aQ = smb + OQ + (uint32_t)((wm * 16 + rsA) * GPH + csA) * 2;
            uint32_t kB = smb + OK + (uint32_t)((wn * 64 + rsB) * GPH + csB) * 2;
            #pragma unroll
            for (int kk = 0; kk < 4; kk++) {
                uint32_t a[4];
                ldsm4(a, aQ + kk * 32);
                #pragma unroll
                for (int kg = 0; kg < 4; kg++) {
                    uint32_t bb[4];
                    ldsm4(bb, kB + kg * 16 * GPH * 2 + kk * 32);
                    mma16(s[kg * 2], a, bb[0], bb[1]);
                    mma16(s[kg * 2 + 1], a, bb[2], bb[3]);
                }
            }
        }

        float pm0 = -INFINITY, pm1 = -INFINITY;
        #pragma unroll
        for (int ng = 0; ng < 8; ng++) {
            int col = wn * 64 + ng * 8 + tig * 2;
            float mv0 = sMask[col] * (-1e9f), mv1 = sMask[col + 1] * (-1e9f);
            s[ng][0] += mv0; s[ng][1] += mv1;
            s[ng][2] += mv0; s[ng][3] += mv1;
            pm0 = fmaxf(pm0, fmaxf(s[ng][0], s[ng][1]));
            pm1 = fmaxf(pm1, fmaxf(s[ng][2], s[ng][3]));
        }
        __syncthreads();
        if (t + 1 < 16) { issueK(t + 1); issueV(t + 1); issueM(t + 1); CP_COMMIT(); }

        pm0 = fmaxf(pm0, __shfl_xor_sync(0xffffffffu, pm0, 1));
        pm0 = fmaxf(pm0, __shfl_xor_sync(0xffffffffu, pm0, 2));
        pm1 = fmaxf(pm1, __shfl_xor_sync(0xffffffffu, pm1, 1));
        pm1 = fmaxf(pm1, __shfl_xor_sync(0xffffffffu, pm1, 2));
        float m_new0 = fmaxf(m_run0, pm0);
        float m_new1 = fmaxf(m_run1, pm1);
        float alpha0 = __expf(m_run0 - m_new0);
        float alpha1 = __expf(m_run1 - m_new1);
        float ps0 = 0.f, ps1 = 0.f;
        #pragma unroll
        for (int ng = 0; ng < 8; ng++) {
            s[ng][0] = __expf(s[ng][0] - m_new0);
            s[ng][1] = __expf(s[ng][1] - m_new0);
            s[ng][2] = __expf(s[ng][2] - m_new1);
            s[ng][3] = __expf(s[ng][3] - m_new1);
            ps0 += s[ng][0] + s[ng][1];
            ps1 += s[ng][2] + s[ng][3];
        }
        ps0 += __shfl_xor_sync(0xffffffffu, ps0, 1);
        ps0 += __shfl_xor_sync(0xffffffffu, ps0, 2);
        ps1 += __shfl_xor_sync(0xffffffffu, ps1, 1);
        ps1 += __shfl_xor_sync(0xffffffffu, ps1, 2);
        l_run0 = l_run0 * alpha0 + ps0;
        l_run1 = l_run1 * alpha1 + ps1;
        m_run0 = m_new0; m_run1 = m_new1;

        uint32_t pf[4][4];
        #pragma unroll
        for (int kc = 0; kc < 4; kc++) {
            pf[kc][0] = h2u(__floats2half2_rn(s[kc * 2][0], s[kc * 2][1]));
            pf[kc][1] = h2u(__floats2half2_rn(s[kc * 2][2], s[kc * 2][3]));
            pf[kc][2] = h2u(__floats2half2_rn(s[kc * 2 + 1][0], s[kc * 2 + 1][1]));
            pf[kc][3] = h2u(__floats2half2_rn(s[kc * 2 + 1][2], s[kc * 2 + 1][3]));
        }

        #pragma unroll
        for (int ng = 0; ng < 8; ng++) {
            o[ng][0] *= alpha0; o[ng][1] *= alpha0;
            o[ng][2] *= alpha1; o[ng][3] *= alpha1;
        }
        {
            uint32_t vB = smb + OV + (t & 1) * OVB + (uint32_t)((wn * 64 + rsA) * GPH + csA) * 2;
            #pragma unroll
            for (int kc = 0; kc < 4; kc++) {
                #pragma unroll
                for (int dg = 0; dg < 4; dg++) {
                    uint32_t bb[4];
                    ldsm4t(bb, vB + (uint32_t)(kc * 16 * GPH + dg * 16) * 2);
                    mma16(o[dg * 2], pf[kc], bb[0], bb[1]);
                    mma16(o[dg * 2 + 1], pf[kc], bb[2], bb[3]);
                }
            }
        }
    }

    float* sM = (float*)(sm + ORM);
    float* sL = (float*)(sm + ORS);
    if (tig == 0) {
        sM[row0 * 2 + wn] = m_run0;  sM[row1 * 2 + wn] = m_run1;
        sL[row0 * 2 + wn] = l_run0;  sL[row1 * 2 + wn] = l_run1;
    }
    __syncthreads();
    float mo0 = sM[row0 * 2 + (wn ^ 1)], mo1 = sM[row1 * 2 + (wn ^ 1)];
    float lo0 = sL[row0 * 2 + (wn ^ 1)], lo1 = sL[row1 * 2 + (wn ^ 1)];
    float mg0 = fmaxf(m_run0, mo0), mg1 = fmaxf(m_run1, mo1);
    float be0 = __expf(m_run0 - mg0), be1 = __expf(m_run1 - mg1);
    float beo0 = __expf(mo0 - mg0),  beo1 = __expf(mo1 - mg1);
    float lg0 = l_run0 * be0 + lo0 * beo0;
    float lg1 = l_run1 * be1 + lo1 * beo1;

    float* sO = (float*)sm;
    if (wn == 1) {
        #pragma unroll
        for (int ng = 0; ng < 8; ng++) {
            *(float2*)&sO[row0 * 68 + ng * 8 + tig * 2] =
                make_float2(o[ng][0] * be0, o[ng][1] * be0);
            *(float2*)&sO[row1 * 68 + ng * 8 + tig * 2] =
                make_float2(o[ng][2] * be1, o[ng][3] * be1);
        }
    }
    __syncthreads();
    if (wn == 0) {
        float inv0 = 1.f / lg0, inv1 = 1.f / lg1;
        #pragma unroll
        for (int ng = 0; ng < 8; ng++) {
            int col = ng * 8 + tig * 2;
            float2 p0 = *(float2*)&sO[row0 * 68 + col];
            float2 p1 = *(float2*)&sO[row1 * 68 + col];
            __half* C0 = C + ((size_t)(b * Sv + q0 + row0)) * Ev + h * 64 + col;
            __half* C1 = C + ((size_t)(b * Sv + q0 + row1)) * Ev + h * 64 + col;
            *(__half2*)C0 = __floats2half2_rn((o[ng][0] * be0 + p0.x) * inv0,
                                              (o[ng][1] * be0 + p0.y) * inv0);
            *(__half2*)C1 = __floats2half2_rn((o[ng][2] * be1 + p1.x) * inv1,
                                              (o[ng][3] * be1 + p1.y) * inv1);
        }
    }
}

// ---------------------------------------------------------------------------
// LayerNorm(pre-added main_out + x), float4 vectorized
// ---------------------------------------------------------------------------
__global__ __launch_bounds__(256) void ln_kernel(const float* __restrict__ MO,
                                                 const float* __restrict__ gamma,
                                                 const float* __restrict__ beta,
                                                 float* __restrict__ out) {
    const int r = blockIdx.x;
    const float* mo = MO + (size_t)r * Ev;

    float4 v = *(const float4*)(mo + threadIdx.x * 4);
    float s1 = v.x + v.y + v.z + v.w;
    float s2 = v.x * v.x + v.y * v.y + v.z * v.z + v.w * v.w;
    #pragma unroll
    for (int o = 16; o > 0; o >>= 1) {
        s1 += __shfl_xor_sync(0xffffffffu, s1, o);
        s2 += __shfl_xor_sync(0xffffffffu, s2, o);
    }
    __shared__ float sh1[8], sh2[8], stats[2];
    const int w = threadIdx.x >> 5, lane = threadIdx.x & 31;
    if (lane == 0) { sh1[w] = s1; sh2[w] = s2; }
    __syncthreads();
    if (threadIdx.x == 0) {
        float t1 = 0.f, t2 = 0.f;
        #pragma unroll
        for (int i = 0; i < 8; i++) { t1 += sh1[i]; t2 += sh2[i]; }
        float mu = t1 * (1.f / Ev);
        float var = t2 * (1.f / Ev) - mu * mu;
        stats[0] = mu;
        stats[1] = rsqrtf(var + 1e-6f);
    }
    __syncthreads();
    const float mu = stats[0], rstd = stats[1];
    float4 g = *(const float4*)(gamma + threadIdx.x * 4);
    float4 be = *(const float4*)(beta + threadIdx.x * 4);
    float4 o;
    o.x = g.x * (v.x - mu) * rstd + be.x;
    o.y = g.y * (v.y - mu) * rstd + be.y;
    o.z = g.z * (v.z - mu) * rstd + be.z;
    o.w = g.w * (v.w - mu) * rstd + be.w;
    *(float4*)(out + (size_t)r * Ev + threadIdx.x * 4) = o;
}

// ---------------------------------------------------------------------------
extern "C" void kernel_launch(void* const* d_in, const int* in_sizes, int n_in,
                              void* d_out, int out_size) {
    const float* x     = (const float*)d_in[0];
    const float* mask  = (const float*)d_in[1];
    const float* Wq    = (const float*)d_in[2];
    const float* bq    = (const float*)d_in[3];
    const float* Wk    = (const float*)d_in[4];
    const float* bk    = (const float*)d_in[5];
    const float* Wv    = (const float*)d_in[6];
    const float* bv    = (const float*)d_in[7];
    const float* Wo    = (const float*)d_in[8];
    const float* bo    = (const float*)d_in[9];
    const float* gamma = (const float*)d_in[10];
    const float* beta  = (const float*)d_in[11];
    float* out = (float*)d_out;

    __half *Xh, *Qh, *Kh, *Vh, *Ch, *WT;
    float *Ob;
    cudaGetSymbolAddress((void**)&Xh, g_Xh);
    cudaGetSymbolAddress((void**)&Qh, g_Qh);
    cudaGetSymbolAddress((void**)&Kh, g_Kh);
    cudaGetSymbolAddress((void**)&Vh, g_Vh);
    cudaGetSymbolAddress((void**)&Ch, g_Ch);
    cudaGetSymbolAddress((void**)&Ob, g_O);
    cudaGetSymbolAddress((void**)&WT, g_WT);
    __half* WTq = WT;
    __half* WTk = WT + 1ull * Ev * Ev;
    __half* WTv = WT + 2ull * Ev * Ev;
    __half* WTo = WT + 3ull * Ev * Ev;

    cudaFuncSetAttribute(gemm_h<true>,  cudaFuncAttributeMaxDynamicSharedMemorySize, GEMM_SMEM);
    cudaFuncSetAttribute(gemm_h<false>, cudaFuncAttributeMaxDynamicSharedMemorySize, GEMM_SMEM);
    cudaFuncSetAttribute(attn_h, cudaFuncAttributeMaxDynamicSharedMemorySize, ATTN_SMEM);

    cvtX<<<BSz * Ev / 1024, 256>>>(x, Xh);
    cvtW4<<<dim3(32, 32, 4), dim3(32, 8)>>>(Wq, Wk, Wv, Wo, WT);

    dim3 gg(8, 64);
    gemm_h<true><<<gg, 256, GEMM_SMEM>>>(Xh, WTq, bq, Qh, 0.03125f, nullptr);
    gemm_h<true><<<gg, 256, GEMM_SMEM>>>(Xh, WTk, bk, Kh, 1.f, nullptr);
    gemm_h<true><<<gg, 256, GEMM_SMEM>>>(Xh, WTv, bv, Vh, 1.f, nullptr);

    attn_h<<<dim3(Sv / 128, Bv * Hv), 512, ATTN_SMEM>>>(Qh, Kh, Vh, mask, Ch);

    gemm_h<false><<<gg, 256, GEMM_SMEM>>>(Ch, WTo, bo, Ob, 1.f, x);

    ln_kernel<<<BSz, 256>>>(Ob, gamma, beta, out);
}